// round 1
// baseline (speedup 1.0000x reference)
#include <cuda_runtime.h>

#define BB 8
#define CC 130
#define CQ 32
#define NN 4096
#define BN_EPS 1e-5f

// Static device scratch (allocation-free rule: __device__ globals)
__device__ float FBUF[BB * CQ * NN];                  // f: [B,32,N]
__device__ float GBUF[BB * CQ * NN];                  // g: [B,32,N]
__device__ float HBUF[BB * CC * NN];                  // h: [B,130,N]
__device__ float SBUF[(size_t)BB * NN * NN];          // s / p: [B,N,N]  (512 MB)

// ---------------------------------------------------------------------------
// K1: fused 1x1-conv + BN + ReLU for all three projections.
// Grid: (N/64, B), 256 threads. x tile [130,64] in smem.
// ---------------------------------------------------------------------------
__global__ __launch_bounds__(256) void proj_kernel(
    const float* __restrict__ x,
    const float* __restrict__ wF, const float* __restrict__ bF,
    const float* __restrict__ fw, const float* __restrict__ fbe,
    const float* __restrict__ fm, const float* __restrict__ fv,
    const float* __restrict__ wG, const float* __restrict__ bG,
    const float* __restrict__ gw, const float* __restrict__ gbe,
    const float* __restrict__ gm, const float* __restrict__ gv,
    const float* __restrict__ wH, const float* __restrict__ bH,
    const float* __restrict__ hw, const float* __restrict__ hbe,
    const float* __restrict__ hm, const float* __restrict__ hv)
{
    __shared__ float xs[CC][64];
    const int b  = blockIdx.y;
    const int n0 = blockIdx.x * 64;
    const int tid = threadIdx.x;

    for (int idx = tid; idx < CC * 64; idx += 256) {
        int c = idx >> 6, i = idx & 63;
        xs[c][i] = x[((size_t)b * CC + c) * NN + n0 + i];
    }
    __syncthreads();

    const int tx = tid & 15;   // 4 columns per thread: n = n0 + tx*4 + u
    const int ty = tid >> 4;   // output-channel stride 16

    for (int o = ty; o < 2 * CQ + CC; o += 16) {
        const float* wrow;
        const float *pb, *pw, *pbe, *pm, *pv;
        float* dst;
        int oo;
        if (o < CQ)          { oo = o;          wrow = wF + oo * CC; pb = bF; pw = fw; pbe = fbe; pm = fm; pv = fv; dst = FBUF + ((size_t)b * CQ + oo) * NN; }
        else if (o < 2 * CQ) { oo = o - CQ;     wrow = wG + oo * CC; pb = bG; pw = gw; pbe = gbe; pm = gm; pv = gv; dst = GBUF + ((size_t)b * CQ + oo) * NN; }
        else                 { oo = o - 2 * CQ; wrow = wH + oo * CC; pb = bH; pw = hw; pbe = hbe; pm = hm; pv = hv; dst = HBUF + ((size_t)b * CC + oo) * NN; }

        float a0 = 0.f, a1 = 0.f, a2 = 0.f, a3 = 0.f;
        #pragma unroll 2
        for (int c = 0; c < CC; c++) {
            float wv = __ldg(wrow + c);
            float4 xv = *(const float4*)&xs[c][tx * 4];
            a0 += wv * xv.x; a1 += wv * xv.y; a2 += wv * xv.z; a3 += wv * xv.w;
        }
        float scale = __ldg(pw + oo) * rsqrtf(__ldg(pv + oo) + BN_EPS);
        float bias  = __ldg(pb + oo) - __ldg(pm + oo);
        float be    = __ldg(pbe + oo);
        float4 r;
        r.x = fmaxf(scale * (a0 + bias) + be, 0.f);
        r.y = fmaxf(scale * (a1 + bias) + be, 0.f);
        r.z = fmaxf(scale * (a2 + bias) + be, 0.f);
        r.w = fmaxf(scale * (a3 + bias) + be, 0.f);
        *(float4*)&dst[n0 + tx * 4] = r;
    }
}

// ---------------------------------------------------------------------------
// K2: s[b,n,m] = sum_c g[b,c,n] * f[b,c,m].  K=32.
// Grid: (N/64 m-tiles, N/64 n-tiles, B), 256 threads, 4x4 per thread.
// ---------------------------------------------------------------------------
__global__ __launch_bounds__(256) void gemm_s_kernel()
{
    __shared__ float gs[CQ][64];
    __shared__ float fs[CQ][64];
    const int b  = blockIdx.z;
    const int m0 = blockIdx.x * 64;
    const int n0 = blockIdx.y * 64;
    const int tid = threadIdx.x;

    for (int idx = tid; idx < CQ * 64; idx += 256) {
        int c = idx >> 6, i = idx & 63;
        gs[c][i] = GBUF[((size_t)b * CQ + c) * NN + n0 + i];
        fs[c][i] = FBUF[((size_t)b * CQ + c) * NN + m0 + i];
    }
    __syncthreads();

    const int tx = tid & 15;   // m sub-tile
    const int ty = tid >> 4;   // n sub-tile
    float acc[4][4] = {};

    #pragma unroll
    for (int c = 0; c < CQ; c++) {
        float4 at = *(const float4*)&gs[c][ty * 4];
        float4 bt = *(const float4*)&fs[c][tx * 4];
        float av[4] = {at.x, at.y, at.z, at.w};
        float bv[4] = {bt.x, bt.y, bt.z, bt.w};
        #pragma unroll
        for (int j = 0; j < 4; j++)
            #pragma unroll
            for (int k = 0; k < 4; k++)
                acc[j][k] += av[j] * bv[k];
    }

    float* srow = SBUF + (size_t)b * NN * NN;
    #pragma unroll
    for (int j = 0; j < 4; j++) {
        float4 r = make_float4(acc[j][0], acc[j][1], acc[j][2], acc[j][3]);
        *(float4*)&srow[(size_t)(n0 + ty * 4 + j) * NN + m0 + tx * 4] = r;
    }
}

// ---------------------------------------------------------------------------
// K3: in-place row softmax over SBUF rows (axis m).
// Grid: B*N blocks, 256 threads; each thread holds 16 elements in registers.
// ---------------------------------------------------------------------------
__global__ __launch_bounds__(256) void softmax_kernel()
{
    float* s = SBUF + (size_t)blockIdx.x * NN;
    const int tid  = threadIdx.x;
    const int lane = tid & 31, warp = tid >> 5;
    __shared__ float red[8];

    float4 v[4];
    #pragma unroll
    for (int q = 0; q < 4; q++)
        v[q] = *(const float4*)&s[tid * 4 + q * 1024];

    float mx = -3.0e38f;
    #pragma unroll
    for (int q = 0; q < 4; q++) {
        mx = fmaxf(mx, fmaxf(fmaxf(v[q].x, v[q].y), fmaxf(v[q].z, v[q].w)));
    }
    #pragma unroll
    for (int off = 16; off; off >>= 1)
        mx = fmaxf(mx, __shfl_xor_sync(0xffffffffu, mx, off));
    if (lane == 0) red[warp] = mx;
    __syncthreads();
    mx = fmaxf(fmaxf(fmaxf(red[0], red[1]), fmaxf(red[2], red[3])),
               fmaxf(fmaxf(red[4], red[5]), fmaxf(red[6], red[7])));
    __syncthreads();

    float sum = 0.f;
    #pragma unroll
    for (int q = 0; q < 4; q++) {
        v[q].x = __expf(v[q].x - mx); sum += v[q].x;
        v[q].y = __expf(v[q].y - mx); sum += v[q].y;
        v[q].z = __expf(v[q].z - mx); sum += v[q].z;
        v[q].w = __expf(v[q].w - mx); sum += v[q].w;
    }
    #pragma unroll
    for (int off = 16; off; off >>= 1)
        sum += __shfl_xor_sync(0xffffffffu, sum, off);
    if (lane == 0) red[warp] = sum;
    __syncthreads();
    float tot = ((red[0] + red[1]) + (red[2] + red[3])) +
                ((red[4] + red[5]) + (red[6] + red[7]));
    float inv = 1.f / tot;

    #pragma unroll
    for (int q = 0; q < 4; q++) {
        v[q].x *= inv; v[q].y *= inv; v[q].z *= inv; v[q].w *= inv;
        *(float4*)&s[tid * 4 + q * 1024] = v[q];
    }
}

// ---------------------------------------------------------------------------
// K4: out[b,c,m] = gamma * sum_n h[b,c,n] * p[b,n,m] + x[b,c,m], c in [0,128)
// Grid: (N/64 m-tiles, B), 256 threads. Tile 128c x 64m x 32k; 8x4 per thread.
// ---------------------------------------------------------------------------
__global__ __launch_bounds__(256) void gemm_o_kernel(
    const float* __restrict__ x, const float* __restrict__ gamma,
    float* __restrict__ out)
{
    __shared__ float hs[128][33];   // padded: avoids 2-addr same-bank LDS
    __shared__ float ps[32][64];
    const int b  = blockIdx.y;
    const int m0 = blockIdx.x * 64;
    const int tid = threadIdx.x;
    const int tx = tid & 15;       // m: m0 + tx*4 + k
    const int ty = tid >> 4;       // c: ty*8 + j

    const float* Hb = HBUF + (size_t)b * CC * NN;
    const float* Pb = SBUF + (size_t)b * NN * NN;

    float acc[8][4] = {};

    for (int nk = 0; nk < NN; nk += 32) {
        // load h tile: 128 x 32 (c rows 0..127, always valid)
        #pragma unroll
        for (int r = 0; r < 4; r++) {
            int idx = tid + r * 256;           // 0..1023 float4 slots
            int cc = idx >> 3, kq = idx & 7;
            float4 hv = *(const float4*)&Hb[(size_t)cc * NN + nk + kq * 4];
            hs[cc][kq * 4 + 0] = hv.x;
            hs[cc][kq * 4 + 1] = hv.y;
            hs[cc][kq * 4 + 2] = hv.z;
            hs[cc][kq * 4 + 3] = hv.w;
        }
        // load p tile: 32 x 64
        #pragma unroll
        for (int r = 0; r < 2; r++) {
            int idx = tid + r * 256;           // 0..511 float4 slots
            int ki = idx >> 4, mq = idx & 15;
            *(float4*)&ps[ki][mq * 4] =
                *(const float4*)&Pb[(size_t)(nk + ki) * NN + m0 + mq * 4];
        }
        __syncthreads();

        #pragma unroll 8
        for (int ki = 0; ki < 32; ki++) {
            float4 bt = *(const float4*)&ps[ki][tx * 4];
            float bv[4] = {bt.x, bt.y, bt.z, bt.w};
            #pragma unroll
            for (int j = 0; j < 8; j++) {
                float a = hs[ty * 8 + j][ki];
                acc[j][0] += a * bv[0];
                acc[j][1] += a * bv[1];
                acc[j][2] += a * bv[2];
                acc[j][3] += a * bv[3];
            }
        }
        __syncthreads();
    }

    const float gm = __ldg(gamma);
    #pragma unroll
    for (int j = 0; j < 8; j++) {
        int c = ty * 8 + j;
        size_t base = ((size_t)b * CC + c) * NN + m0 + tx * 4;
        float4 xv = *(const float4*)&x[base];
        float4 r = make_float4(gm * acc[j][0] + xv.x,
                               gm * acc[j][1] + xv.y,
                               gm * acc[j][2] + xv.z,
                               gm * acc[j][3] + xv.w);
        *(float4*)&out[base] = r;
    }
}

// ---------------------------------------------------------------------------
// K5: tail rows c = 128, 129.
// Grid: (N/128, B), 256 threads, one (c,m) output per thread.
// ---------------------------------------------------------------------------
__global__ __launch_bounds__(256) void gemm_o_tail_kernel(
    const float* __restrict__ x, const float* __restrict__ gamma,
    float* __restrict__ out)
{
    __shared__ float ps[32][128];
    __shared__ float hs2[2][32];
    const int b  = blockIdx.y;
    const int m0 = blockIdx.x * 128;
    const int tid = threadIdx.x;
    const int cc = tid >> 7;        // 0 or 1
    const int mi = tid & 127;

    const float* Hb = HBUF + (size_t)b * CC * NN;
    const float* Pb = SBUF + (size_t)b * NN * NN;

    float acc = 0.f;
    for (int nk = 0; nk < NN; nk += 32) {
        #pragma unroll
        for (int r = 0; r < 4; r++) {
            int idx = tid + r * 256;           // 0..1023 float4 slots
            int ki = idx >> 5, mq = idx & 31;
            *(float4*)&ps[ki][mq * 4] =
                *(const float4*)&Pb[(size_t)(nk + ki) * NN + m0 + mq * 4];
        }
        if (tid < 64)
            hs2[tid >> 5][tid & 31] = Hb[(size_t)(128 + (tid >> 5)) * NN + nk + (tid & 31)];
        __syncthreads();
        #pragma unroll
        for (int ki = 0; ki < 32; ki++)
            acc += hs2[cc][ki] * ps[ki][mi];
        __syncthreads();
    }

    size_t base = ((size_t)b * CC + 128 + cc) * NN + m0 + mi;
    out[base] = __ldg(gamma) * acc + x[base];
}

// ---------------------------------------------------------------------------
extern "C" void kernel_launch(void* const* d_in, const int* in_sizes, int n_in,
                              void* d_out, int out_size)
{
    const float* x   = (const float*)d_in[0];
    const float* wF  = (const float*)d_in[1];
    const float* bF  = (const float*)d_in[2];
    const float* fw  = (const float*)d_in[3];
    const float* fbe = (const float*)d_in[4];
    const float* fm  = (const float*)d_in[5];
    const float* fv  = (const float*)d_in[6];
    const float* wG  = (const float*)d_in[7];
    const float* bG  = (const float*)d_in[8];
    const float* gw  = (const float*)d_in[9];
    const float* gbe = (const float*)d_in[10];
    const float* gm  = (const float*)d_in[11];
    const float* gv  = (const float*)d_in[12];
    const float* wH  = (const float*)d_in[13];
    const float* bH  = (const float*)d_in[14];
    const float* hw  = (const float*)d_in[15];
    const float* hbe = (const float*)d_in[16];
    const float* hm  = (const float*)d_in[17];
    const float* hv  = (const float*)d_in[18];
    const float* gamma = (const float*)d_in[19];
    float* out = (float*)d_out;

    proj_kernel<<<dim3(NN / 64, BB), 256>>>(x,
        wF, bF, fw, fbe, fm, fv,
        wG, bG, gw, gbe, gm, gv,
        wH, bH, hw, hbe, hm, hv);
    gemm_s_kernel<<<dim3(NN / 64, NN / 64, BB), 256>>>();
    softmax_kernel<<<BB * NN, 256>>>();
    gemm_o_kernel<<<dim3(NN / 64, BB), 256>>>(x, gamma, out);
    gemm_o_tail_kernel<<<dim3(NN / 128, BB), 256>>>(x, gamma, out);
}

// round 3
// speedup vs baseline: 1.7755x; 1.7755x over previous
#include <cuda_runtime.h>
#include <cuda_bf16.h>
#include <cstdint>

#define BB 8
#define CC 130
#define CPAD 144          // c padded to 9 x 16 for MMA M tiles
#define CQ 32
#define NN 4096
#define BN_EPS 1e-5f

// ---------------- static device scratch ----------------
__device__ float FBUF[BB * CQ * NN];
__device__ float GBUF[BB * CQ * NN];
__device__ float HF[(size_t)BB * CPAD * NN];            // h fp32 (pre-scale)
__device__ __nv_bfloat16 HHB[(size_t)BB * CPAD * NN];   // h' = h*invZ, hi
__device__ __nv_bfloat16 HLB[(size_t)BB * CPAD * NN];   // h' lo
__device__ float SBUF[(size_t)BB * NN * NN];            // raw logits s
__device__ __nv_bfloat16 PTH[(size_t)BB * NN * NN];     // e^T hi: [b][m][n]
__device__ __nv_bfloat16 PTL[(size_t)BB * NN * NN];     // e^T lo
__device__ float PMAX[(size_t)BB * NN * 64];
__device__ float PSUM[(size_t)BB * NN * 64];
__device__ float ROWM[BB * NN];
__device__ float ROWI[BB * NN];

// ---------------- helpers ----------------
__device__ __forceinline__ uint32_t smem_u32(const void* p) {
    uint32_t a;
    asm("{ .reg .u64 t; cvta.to.shared.u64 t, %1; cvt.u32.u64 %0, t; }" : "=r"(a) : "l"(p));
    return a;
}
__device__ __forceinline__ void cpa16(uint32_t dst, const void* src) {
    asm volatile("cp.async.cg.shared.global [%0], [%1], 16;" :: "r"(dst), "l"(src));
}
#define CP_COMMIT() asm volatile("cp.async.commit_group;" ::: "memory")
#define CP_WAIT1()  asm volatile("cp.async.wait_group 1;" ::: "memory")
#define CP_WAIT0()  asm volatile("cp.async.wait_group 0;" ::: "memory")

__device__ __forceinline__ void ldsm4(uint32_t* r, uint32_t addr) {
    asm volatile("ldmatrix.sync.aligned.m8n8.x4.shared.b16 {%0,%1,%2,%3}, [%4];"
                 : "=r"(r[0]), "=r"(r[1]), "=r"(r[2]), "=r"(r[3]) : "r"(addr));
}
__device__ __forceinline__ void ldsm2(uint32_t* r, uint32_t addr) {
    asm volatile("ldmatrix.sync.aligned.m8n8.x2.shared.b16 {%0,%1}, [%2];"
                 : "=r"(r[0]), "=r"(r[1]) : "r"(addr));
}
__device__ __forceinline__ void mma16816(float* d, const uint32_t* a, const uint32_t* b) {
    asm volatile("mma.sync.aligned.m16n8k16.row.col.f32.bf16.bf16.f32 "
                 "{%0,%1,%2,%3}, {%4,%5,%6,%7}, {%8,%9}, {%0,%1,%2,%3};"
                 : "+f"(d[0]), "+f"(d[1]), "+f"(d[2]), "+f"(d[3])
                 : "r"(a[0]), "r"(a[1]), "r"(a[2]), "r"(a[3]), "r"(b[0]), "r"(b[1]));
}

// ---------------------------------------------------------------------------
// K1: fused 1x1-conv + BN + ReLU. F,G -> fp32; H -> fp32 HF (+ zero pad rows)
// ---------------------------------------------------------------------------
__global__ __launch_bounds__(256) void proj_kernel(
    const float* __restrict__ x,
    const float* __restrict__ wF, const float* __restrict__ bF,
    const float* __restrict__ fw, const float* __restrict__ fbe,
    const float* __restrict__ fm, const float* __restrict__ fv,
    const float* __restrict__ wG, const float* __restrict__ bG,
    const float* __restrict__ gw, const float* __restrict__ gbe,
    const float* __restrict__ gm, const float* __restrict__ gv,
    const float* __restrict__ wH, const float* __restrict__ bH,
    const float* __restrict__ hw, const float* __restrict__ hbe,
    const float* __restrict__ hm, const float* __restrict__ hv)
{
    __shared__ float xs[CC][64];
    const int b  = blockIdx.y;
    const int n0 = blockIdx.x * 64;
    const int tid = threadIdx.x;

    for (int idx = tid; idx < CC * 64; idx += 256) {
        int c = idx >> 6, i = idx & 63;
        xs[c][i] = x[((size_t)b * CC + c) * NN + n0 + i];
    }
    __syncthreads();

    const int tx = tid & 15;
    const int ty = tid >> 4;

    for (int o = ty; o < 2 * CQ + CPAD; o += 16) {
        if (o >= 2 * CQ + CC) {
            int oo = o - 2 * CQ;    // pad rows [130,144): zero
            *(float4*)&HF[((size_t)b * CPAD + oo) * NN + n0 + tx * 4] =
                make_float4(0.f, 0.f, 0.f, 0.f);
            continue;
        }
        const float* wrow;
        const float *pb, *pw, *pbe, *pm, *pv;
        int oo, which;
        if (o < CQ)          { oo = o;          which = 0; wrow = wF + oo * CC; pb = bF; pw = fw; pbe = fbe; pm = fm; pv = fv; }
        else if (o < 2 * CQ) { oo = o - CQ;     which = 1; wrow = wG + oo * CC; pb = bG; pw = gw; pbe = gbe; pm = gm; pv = gv; }
        else                 { oo = o - 2 * CQ; which = 2; wrow = wH + oo * CC; pb = bH; pw = hw; pbe = hbe; pm = hm; pv = hv; }

        float a0 = 0.f, a1 = 0.f, a2 = 0.f, a3 = 0.f;
        #pragma unroll 2
        for (int c = 0; c < CC; c++) {
            float wv = __ldg(wrow + c);
            float4 xv = *(const float4*)&xs[c][tx * 4];
            a0 += wv * xv.x; a1 += wv * xv.y; a2 += wv * xv.z; a3 += wv * xv.w;
        }
        float scale = __ldg(pw + oo) * rsqrtf(__ldg(pv + oo) + BN_EPS);
        float bias  = __ldg(pb + oo) - __ldg(pm + oo);
        float be    = __ldg(pbe + oo);
        float4 r;
        r.x = fmaxf(scale * (a0 + bias) + be, 0.f);
        r.y = fmaxf(scale * (a1 + bias) + be, 0.f);
        r.z = fmaxf(scale * (a2 + bias) + be, 0.f);
        r.w = fmaxf(scale * (a3 + bias) + be, 0.f);
        if (which == 2) {
            *(float4*)&HF[((size_t)b * CPAD + oo) * NN + n0 + tx * 4] = r;
        } else {
            float* dst = (which == 0 ? FBUF : GBUF) + ((size_t)b * CQ + oo) * NN;
            *(float4*)&dst[n0 + tx * 4] = r;
        }
    }
}

// ---------------------------------------------------------------------------
// K2: s[b,n,m] = sum_c g[b,c,n]*f[b,c,m]; per-(row,64-m-tile) max partials
// ---------------------------------------------------------------------------
__global__ __launch_bounds__(256) void gemm_s_kernel()
{
    __shared__ float gs[CQ][64];
    __shared__ float fs[CQ][64];
    const int b  = blockIdx.z;
    const int m0 = blockIdx.x * 64;
    const int n0 = blockIdx.y * 64;
    const int tid = threadIdx.x;

    for (int idx = tid; idx < CQ * 64; idx += 256) {
        int c = idx >> 6, i = idx & 63;
        gs[c][i] = GBUF[((size_t)b * CQ + c) * NN + n0 + i];
        fs[c][i] = FBUF[((size_t)b * CQ + c) * NN + m0 + i];
    }
    __syncthreads();

    const int tx = tid & 15;
    const int ty = tid >> 4;
    float acc[4][4] = {};

    #pragma unroll
    for (int c = 0; c < CQ; c++) {
        float4 at = *(const float4*)&gs[c][ty * 4];
        float4 bt = *(const float4*)&fs[c][tx * 4];
        float av[4] = {at.x, at.y, at.z, at.w};
        float bv[4] = {bt.x, bt.y, bt.z, bt.w};
        #pragma unroll
        for (int j = 0; j < 4; j++)
            #pragma unroll
            for (int k = 0; k < 4; k++)
                acc[j][k] += av[j] * bv[k];
    }

    float* srow = SBUF + (size_t)b * NN * NN;
    #pragma unroll
    for (int j = 0; j < 4; j++) {
        *(float4*)&srow[(size_t)(n0 + ty * 4 + j) * NN + m0 + tx * 4] =
            make_float4(acc[j][0], acc[j][1], acc[j][2], acc[j][3]);
    }

    #pragma unroll
    for (int j = 0; j < 4; j++) {
        float mx = fmaxf(fmaxf(acc[j][0], acc[j][1]), fmaxf(acc[j][2], acc[j][3]));
        #pragma unroll
        for (int off = 8; off; off >>= 1)
            mx = fmaxf(mx, __shfl_xor_sync(0xffffffffu, mx, off));
        if (tx == 0) {
            size_t r = (size_t)b * NN + n0 + ty * 4 + j;
            PMAX[r * 64 + blockIdx.x] = mx;
        }
    }
}

// ---------------------------------------------------------------------------
// K3a: row max over 64 partials
// ---------------------------------------------------------------------------
__global__ __launch_bounds__(256) void reduce_max_kernel()
{
    int r = blockIdx.x * 8 + (threadIdx.x >> 5);
    int lane = threadIdx.x & 31;
    const float* pm = PMAX + (size_t)r * 64;
    float M = fmaxf(pm[lane], pm[lane + 32]);
    #pragma unroll
    for (int off = 16; off; off >>= 1)
        M = fmaxf(M, __shfl_xor_sync(0xffffffffu, M, off));
    if (lane == 0) ROWM[r] = M;
}

// ---------------------------------------------------------------------------
// K3b: e = exp(S - M) -> transposed bf16 hi/lo (unnormalized) + sum partials
// ---------------------------------------------------------------------------
__global__ __launch_bounds__(256) void softmax_t_kernel()
{
    __shared__ float ts[64][65];
    const int b  = blockIdx.z;
    const int n0 = blockIdx.y * 64;
    const int m0 = blockIdx.x * 64;
    const int t  = threadIdx.x;

    // read side: 4 threads per n-row, coalesced along m; also sum partials
    {
        int nl = t >> 2, ms = (t & 3) * 16;
        size_t rown = (size_t)b * NN + n0 + nl;
        float M = __ldg(&ROWM[rown]);
        const float* srow = SBUF + rown * NN + m0 + ms;
        float psum = 0.f;
        #pragma unroll
        for (int i = 0; i < 4; i++) {
            float4 v = *(const float4*)(srow + i * 4);
            float e0 = __expf(v.x - M), e1 = __expf(v.y - M);
            float e2 = __expf(v.z - M), e3 = __expf(v.w - M);
            ts[nl][ms + i * 4 + 0] = e0;
            ts[nl][ms + i * 4 + 1] = e1;
            ts[nl][ms + i * 4 + 2] = e2;
            ts[nl][ms + i * 4 + 3] = e3;
            psum += (e0 + e1) + (e2 + e3);
        }
        psum += __shfl_xor_sync(0xffffffffu, psum, 1);
        psum += __shfl_xor_sync(0xffffffffu, psum, 2);
        if ((t & 3) == 0) PSUM[rown * 64 + blockIdx.x] = psum;
    }
    __syncthreads();

    // write side: transposed, coalesced along n
    {
        int w = t >> 5, l = t & 31;
        int ml = w * 8 + (l >> 2);
        int ns = (l & 3) * 16;
        __nv_bfloat16 hi[16], lo[16];
        #pragma unroll
        for (int i = 0; i < 16; i++) {
            float p = ts[ns + i][ml];
            hi[i] = __float2bfloat16(p);
            lo[i] = __float2bfloat16(p - __bfloat162float(hi[i]));
        }
        size_t dst = ((size_t)b * NN + m0 + ml) * NN + n0 + ns;
        *(uint4*)&PTH[dst]     = ((uint4*)hi)[0];
        *(uint4*)&PTH[dst + 8] = ((uint4*)hi)[1];
        *(uint4*)&PTL[dst]     = ((uint4*)lo)[0];
        *(uint4*)&PTL[dst + 8] = ((uint4*)lo)[1];
    }
}

// ---------------------------------------------------------------------------
// K3c: ROWI = 1 / sum of 64 partials
// ---------------------------------------------------------------------------
__global__ __launch_bounds__(256) void reduce_sum_kernel()
{
    int r = blockIdx.x * 8 + (threadIdx.x >> 5);
    int lane = threadIdx.x & 31;
    const float* ps = PSUM + (size_t)r * 64;
    float z = ps[lane] + ps[lane + 32];
    #pragma unroll
    for (int off = 16; off; off >>= 1)
        z += __shfl_xor_sync(0xffffffffu, z, off);
    if (lane == 0) ROWI[r] = 1.f / z;
}

// ---------------------------------------------------------------------------
// K3d: h'[b,c,n] = HF[b,c,n] * ROWI[b,n] -> bf16 hi/lo
// ---------------------------------------------------------------------------
__global__ __launch_bounds__(256) void scale_h_kernel()
{
    const int b = blockIdx.x / CPAD;
    const int c = blockIdx.x % CPAD;
    const float* hrow = HF + ((size_t)b * CPAD + c) * NN;
    const float* zrow = ROWI + (size_t)b * NN;
    __nv_bfloat16* dh = HHB + ((size_t)b * CPAD + c) * NN;
    __nv_bfloat16* dl = HLB + ((size_t)b * CPAD + c) * NN;

    for (int i = threadIdx.x; i < NN / 4; i += 256) {
        float4 h = *(const float4*)&hrow[i * 4];
        float4 z = *(const float4*)&zrow[i * 4];
        float v[4] = {h.x * z.x, h.y * z.y, h.z * z.z, h.w * z.w};
        __nv_bfloat16 hi[4], lo[4];
        #pragma unroll
        for (int k = 0; k < 4; k++) {
            hi[k] = __float2bfloat16(v[k]);
            lo[k] = __float2bfloat16(v[k] - __bfloat162float(hi[k]));
        }
        *(uint2*)&dh[i * 4] = *(uint2*)hi;
        *(uint2*)&dl[i * 4] = *(uint2*)lo;
    }
}

// ---------------------------------------------------------------------------
// K4: mma.sync bf16x3 GEMM.  D[c(144), m(128/block)] = sum_n H'[c,n]*e[n,m]
// out = gamma * D + x.  Grid (32, 8), 256 threads (8 warps: 2 c x 4 m).
// Smem: 2 stages x { Ah 144x64, Al, Bh 128x64, Bl } bf16, XOR-swizzled rows.
// ---------------------------------------------------------------------------
#define KB 64
#define ST_AH 0
#define ST_AL 18432
#define ST_BH 36864
#define ST_BL 53248
#define ST_BYTES 69632
#define SMEM_DYN (2 * ST_BYTES + 128)

__global__ __launch_bounds__(256, 1) void gemm_o_mma_kernel(
    const float* __restrict__ x, const float* __restrict__ gamma,
    float* __restrict__ out)
{
    extern __shared__ char smem_raw[];
    const uint32_t sb = (smem_u32(smem_raw) + 127) & ~127u;

    const int tid  = threadIdx.x;
    const int w    = tid >> 5;
    const int lane = tid & 31;
    const int cw   = w >> 2;           // 0 or 1
    const int mw   = w & 3;            // 0..3
    const int nct  = (cw == 0) ? 5 : 4; // c-tiles per warp (5/4 split of 9)
    const int b    = blockIdx.y;
    const int m0   = blockIdx.x * 128;

    const size_t abase = (size_t)b * CPAD;       // H' rows (c)
    const size_t bbase = (size_t)b * NN + m0;    // e^T rows (m)

    // ---- stage loader ----
    auto load_stage = [&](int st, int nk) {
        uint32_t base = sb + st * ST_BYTES;
        // A: H' hi/lo, 144 rows x 8 16B-chunks each, x2 buffers = 2304
        for (int t = tid; t < 2304; t += 256) {
            int buf = t >= 1152;
            int idx = t - (buf ? 1152 : 0);
            int row = idx >> 3, q = idx & 7;
            const __nv_bfloat16* src =
                (buf ? HLB : HHB) + ((abase + row) << 12) + nk + q * 8;
            cpa16(base + (buf ? ST_AL : ST_AH) + row * 128 + ((q ^ (row & 7)) << 4), src);
        }
        // B: e^T hi/lo, 128 rows x 8 chunks, x2 = 2048
        for (int t = tid; t < 2048; t += 256) {
            int buf = t >= 1024;
            int idx = t - (buf ? 1024 : 0);
            int row = idx >> 3, q = idx & 7;
            const __nv_bfloat16* src =
                (buf ? PTL : PTH) + ((bbase + row) << 12) + nk + q * 8;
            cpa16(base + (buf ? ST_BL : ST_BH) + row * 128 + ((q ^ (row & 7)) << 4), src);
        }
    };

    float acc[5][4][4] = {};

    load_stage(0, 0);
    CP_COMMIT();

    const int a_roff = ((lane >> 3) & 1) * 8 + (lane & 7);  // row offset in m16 tile
    const int a_koff = lane >> 4;                            // k-chunk offset
    const int bl     = lane & 15;
    const int b_roff = bl & 7;
    const int b_koff = bl >> 3;

    for (int chunk = 0; chunk < NN / KB; chunk++) {
        int cur = chunk & 1;
        if (chunk + 1 < NN / KB) {
            load_stage(cur ^ 1, (chunk + 1) * KB);
            CP_COMMIT();
            CP_WAIT1();
        } else {
            CP_WAIT0();
        }
        __syncthreads();

        uint32_t base = sb + cur * ST_BYTES;
        #pragma unroll
        for (int ks = 0; ks < 4; ks++) {
            uint32_t Ah[5][4], Al[5][4], Bh[4][2], Bl[4][2];
            #pragma unroll
            for (int ct = 0; ct < 5; ct++) {
                if (ct < nct) {
                    int row = cw * 80 + ct * 16 + a_roff;
                    int kch = ks * 2 + a_koff;
                    uint32_t off = row * 128 + ((kch ^ (row & 7)) << 4);
                    ldsm4(Ah[ct], base + ST_AH + off);
                    ldsm4(Al[ct], base + ST_AL + off);
                }
            }
            #pragma unroll
            for (int mt = 0; mt < 4; mt++) {
                int row = mw * 32 + mt * 8 + b_roff;
                int kch = ks * 2 + b_koff;
                uint32_t off = row * 128 + ((kch ^ (row & 7)) << 4);
                ldsm2(Bh[mt], base + ST_BH + off);
                ldsm2(Bl[mt], base + ST_BL + off);
            }
            #pragma unroll
            for (int ct = 0; ct < 5; ct++) {
                if (ct < nct) {
                    #pragma unroll
                    for (int mt = 0; mt < 4; mt++) {
                        mma16816(acc[ct][mt], Ah[ct], Bh[mt]);
                        mma16816(acc[ct][mt], Ah[ct], Bl[mt]);
                        mma16816(acc[ct][mt], Al[ct], Bh[mt]);
                    }
                }
            }
        }
        __syncthreads();
    }

    // ---- epilogue: out = gamma*D + x ----
    const float gm = __ldg(gamma);
    const int g = lane >> 2;
    const int mo = (lane & 3) * 2;
    #pragma unroll
    for (int ct = 0; ct < 5; ct++) {
        if (ct >= nct) break;
        int c0 = cw * 80 + ct * 16 + g;
        #pragma unroll
        for (int mt = 0; mt < 4; mt++) {
            int m = m0 + mw * 32 + mt * 8 + mo;
            if (c0 < CC) {
                size_t idx = ((size_t)b * CC + c0) * NN + m;
                float2 xv = *(const float2*)&x[idx];
                *(float2*)&out[idx] = make_float2(gm * acc[ct][mt][0] + xv.x,
                                                  gm * acc[ct][mt][1] + xv.y);
            }
            if (c0 + 8 < CC) {
                size_t idx = ((size_t)b * CC + c0 + 8) * NN + m;
                float2 xv = *(const float2*)&x[idx];
                *(float2*)&out[idx] = make_float2(gm * acc[ct][mt][2] + xv.x,
                                                  gm * acc[ct][mt][3] + xv.y);
            }
        }
    }
}

// ---------------------------------------------------------------------------
extern "C" void kernel_launch(void* const* d_in, const int* in_sizes, int n_in,
                              void* d_out, int out_size)
{
    const float* x   = (const float*)d_in[0];
    const float* wF  = (const float*)d_in[1];
    const float* bF  = (const float*)d_in[2];
    const float* fw  = (const float*)d_in[3];
    const float* fbe = (const float*)d_in[4];
    const float* fm  = (const float*)d_in[5];
    const float* fv  = (const float*)d_in[6];
    const float* wG  = (const float*)d_in[7];
    const float* bG  = (const float*)d_in[8];
    const float* gw  = (const float*)d_in[9];
    const float* gbe = (const float*)d_in[10];
    const float* gm  = (const float*)d_in[11];
    const float* gv  = (const float*)d_in[12];
    const float* wH  = (const float*)d_in[13];
    const float* bH  = (const float*)d_in[14];
    const float* hw  = (const float*)d_in[15];
    const float* hbe = (const float*)d_in[16];
    const float* hm  = (const float*)d_in[17];
    const float* hv  = (const float*)d_in[18];
    const float* gamma = (const float*)d_in[19];
    float* out = (float*)d_out;

    cudaFuncSetAttribute(gemm_o_mma_kernel,
                         cudaFuncAttributeMaxDynamicSharedMemorySize, SMEM_DYN);

    proj_kernel<<<dim3(NN / 64, BB), 256>>>(x,
        wF, bF, fw, fbe, fm, fv,
        wG, bG, gw, gbe, gm, gv,
        wH, bH, hw, hbe, hm, hv);
    gemm_s_kernel<<<dim3(NN / 64, NN / 64, BB), 256>>>();
    reduce_max_kernel<<<BB * NN / 8, 256>>>();
    softmax_t_kernel<<<dim3(NN / 64, NN / 64, BB), 256>>>();
    reduce_sum_kernel<<<BB * NN / 8, 256>>>();
    scale_h_kernel<<<BB * CPAD, 256>>>();
    gemm_o_mma_kernel<<<dim3(NN / 128, BB), 256, SMEM_DYN>>>(x, gamma, out);
}

// round 4
// speedup vs baseline: 1.9969x; 1.1247x over previous
#include <cuda_runtime.h>
#include <cuda_bf16.h>
#include <cstdint>

#define BB 8
#define CC 130
#define CPAD 144          // c padded to 9 x 16 for MMA M tiles
#define CQ 32
#define NN 4096
#define BN_EPS 1e-5f

// ---------------- static device scratch ----------------
__device__ float FBUF[BB * CQ * NN];
__device__ float GBUF[BB * CQ * NN];
__device__ float HF[(size_t)BB * CPAD * NN];            // h fp32 (pre-scale)
__device__ __nv_bfloat16 HHB[(size_t)BB * CPAD * NN];   // h' = h*invZ, hi
__device__ __nv_bfloat16 HLB[(size_t)BB * CPAD * NN];   // h' lo
__device__ float SBUF[(size_t)BB * NN * NN];            // raw logits s
__device__ __nv_bfloat16 PTH[(size_t)BB * NN * NN];     // e^T hi: [b][m][n]
__device__ float PMAX[(size_t)BB * NN * 64];
__device__ float PSUM[(size_t)BB * NN * 64];
__device__ float ROWM[BB * NN];
__device__ float ROWI[BB * NN];

// ---------------- helpers ----------------
__device__ __forceinline__ uint32_t smem_u32(const void* p) {
    uint32_t a;
    asm("{ .reg .u64 t; cvta.to.shared.u64 t, %1; cvt.u32.u64 %0, t; }" : "=r"(a) : "l"(p));
    return a;
}
__device__ __forceinline__ void cpa16(uint32_t dst, const void* src) {
    asm volatile("cp.async.cg.shared.global [%0], [%1], 16;" :: "r"(dst), "l"(src));
}
#define CP_COMMIT() asm volatile("cp.async.commit_group;" ::: "memory")
#define CP_WAIT1()  asm volatile("cp.async.wait_group 1;" ::: "memory")
#define CP_WAIT0()  asm volatile("cp.async.wait_group 0;" ::: "memory")

__device__ __forceinline__ void ldsm4(uint32_t* r, uint32_t addr) {
    asm volatile("ldmatrix.sync.aligned.m8n8.x4.shared.b16 {%0,%1,%2,%3}, [%4];"
                 : "=r"(r[0]), "=r"(r[1]), "=r"(r[2]), "=r"(r[3]) : "r"(addr));
}
__device__ __forceinline__ void ldsm2(uint32_t* r, uint32_t addr) {
    asm volatile("ldmatrix.sync.aligned.m8n8.x2.shared.b16 {%0,%1}, [%2];"
                 : "=r"(r[0]), "=r"(r[1]) : "r"(addr));
}
__device__ __forceinline__ void mma16816(float* d, const uint32_t* a, const uint32_t* b) {
    asm volatile("mma.sync.aligned.m16n8k16.row.col.f32.bf16.bf16.f32 "
                 "{%0,%1,%2,%3}, {%4,%5,%6,%7}, {%8,%9}, {%0,%1,%2,%3};"
                 : "+f"(d[0]), "+f"(d[1]), "+f"(d[2]), "+f"(d[3])
                 : "r"(a[0]), "r"(a[1]), "r"(a[2]), "r"(a[3]), "r"(b[0]), "r"(b[1]));
}

// ---------------------------------------------------------------------------
// K1: fused 1x1-conv + BN + ReLU. F,G -> fp32; H -> fp32 HF (+ zero pad rows)
// ---------------------------------------------------------------------------
__global__ __launch_bounds__(256) void proj_kernel(
    const float* __restrict__ x,
    const float* __restrict__ wF, const float* __restrict__ bF,
    const float* __restrict__ fw, const float* __restrict__ fbe,
    const float* __restrict__ fm, const float* __restrict__ fv,
    const float* __restrict__ wG, const float* __restrict__ bG,
    const float* __restrict__ gw, const float* __restrict__ gbe,
    const float* __restrict__ gm, const float* __restrict__ gv,
    const float* __restrict__ wH, const float* __restrict__ bH,
    const float* __restrict__ hw, const float* __restrict__ hbe,
    const float* __restrict__ hm, const float* __restrict__ hv)
{
    __shared__ float xs[CC][64];
    const int b  = blockIdx.y;
    const int n0 = blockIdx.x * 64;
    const int tid = threadIdx.x;

    for (int idx = tid; idx < CC * 64; idx += 256) {
        int c = idx >> 6, i = idx & 63;
        xs[c][i] = x[((size_t)b * CC + c) * NN + n0 + i];
    }
    __syncthreads();

    const int tx = tid & 15;
    const int ty = tid >> 4;

    for (int o = ty; o < 2 * CQ + CPAD; o += 16) {
        if (o >= 2 * CQ + CC) {
            int oo = o - 2 * CQ;    // pad rows [130,144): zero
            *(float4*)&HF[((size_t)b * CPAD + oo) * NN + n0 + tx * 4] =
                make_float4(0.f, 0.f, 0.f, 0.f);
            continue;
        }
        const float* wrow;
        const float *pb, *pw, *pbe, *pm, *pv;
        int oo, which;
        if (o < CQ)          { oo = o;          which = 0; wrow = wF + oo * CC; pb = bF; pw = fw; pbe = fbe; pm = fm; pv = fv; }
        else if (o < 2 * CQ) { oo = o - CQ;     which = 1; wrow = wG + oo * CC; pb = bG; pw = gw; pbe = gbe; pm = gm; pv = gv; }
        else                 { oo = o - 2 * CQ; which = 2; wrow = wH + oo * CC; pb = bH; pw = hw; pbe = hbe; pm = hm; pv = hv; }

        float a0 = 0.f, a1 = 0.f, a2 = 0.f, a3 = 0.f;
        #pragma unroll 2
        for (int c = 0; c < CC; c++) {
            float wv = __ldg(wrow + c);
            float4 xv = *(const float4*)&xs[c][tx * 4];
            a0 += wv * xv.x; a1 += wv * xv.y; a2 += wv * xv.z; a3 += wv * xv.w;
        }
        float scale = __ldg(pw + oo) * rsqrtf(__ldg(pv + oo) + BN_EPS);
        float bias  = __ldg(pb + oo) - __ldg(pm + oo);
        float be    = __ldg(pbe + oo);
        float4 r;
        r.x = fmaxf(scale * (a0 + bias) + be, 0.f);
        r.y = fmaxf(scale * (a1 + bias) + be, 0.f);
        r.z = fmaxf(scale * (a2 + bias) + be, 0.f);
        r.w = fmaxf(scale * (a3 + bias) + be, 0.f);
        if (which == 2) {
            *(float4*)&HF[((size_t)b * CPAD + oo) * NN + n0 + tx * 4] = r;
        } else {
            float* dst = (which == 0 ? FBUF : GBUF) + ((size_t)b * CQ + oo) * NN;
            *(float4*)&dst[n0 + tx * 4] = r;
        }
    }
}

// ---------------------------------------------------------------------------
// K2: tensor-core s = g^T f (bf16x3, K=32). Block: 128n x 128m, 8 warps (4x2).
// Writes S fp32 + per-(row, 64-m) max partials into PMAX[.., 64].
// ---------------------------------------------------------------------------
__global__ __launch_bounds__(256) void gemm_s_mma_kernel()
{
    __shared__ __align__(16) __nv_bfloat16 gh[128][40];
    __shared__ __align__(16) __nv_bfloat16 gl[128][40];
    __shared__ __align__(16) __nv_bfloat16 fh[128][40];
    __shared__ __align__(16) __nv_bfloat16 fl[128][40];

    const int b  = blockIdx.z;
    const int m0 = blockIdx.x * 128;
    const int n0 = blockIdx.y * 128;
    const int tid = threadIdx.x;

    // load fp32 coalesced, convert to bf16 hi/lo, store transposed [pos][c]
    for (int idx = tid; idx < CQ * 128; idx += 256) {
        int c = idx >> 7, i = idx & 127;
        float gv = GBUF[((size_t)b * CQ + c) * NN + n0 + i];
        float fv = FBUF[((size_t)b * CQ + c) * NN + m0 + i];
        __nv_bfloat16 h1 = __float2bfloat16(gv);
        gh[i][c] = h1;
        gl[i][c] = __float2bfloat16(gv - __bfloat162float(h1));
        __nv_bfloat16 h2 = __float2bfloat16(fv);
        fh[i][c] = h2;
        fl[i][c] = __float2bfloat16(fv - __bfloat162float(h2));
    }
    __syncthreads();

    const int w = tid >> 5, lane = tid & 31;
    const int nw = w >> 1, mw = w & 1;
    const int a_roff = ((lane >> 3) & 1) * 8 + (lane & 7);
    const int a_koff = lane >> 4;
    const int bl = lane & 15;
    const int b_roff = bl & 7, b_koff = bl >> 3;

    const uint32_t gh_b = smem_u32(gh), gl_b = smem_u32(gl);
    const uint32_t fh_b = smem_u32(fh), fl_b = smem_u32(fl);

    float acc[2][8][4] = {};

    #pragma unroll
    for (int ks = 0; ks < 2; ks++) {
        uint32_t Ah[2][4], Al[2][4], Bh[8][2], Bl[8][2];
        #pragma unroll
        for (int at = 0; at < 2; at++) {
            int row = nw * 32 + at * 16 + a_roff;
            uint32_t off = row * 80 + ks * 32 + a_koff * 16;
            ldsm4(Ah[at], gh_b + off);
            ldsm4(Al[at], gl_b + off);
        }
        #pragma unroll
        for (int bt = 0; bt < 8; bt++) {
            int row = mw * 64 + bt * 8 + b_roff;
            uint32_t off = row * 80 + ks * 32 + b_koff * 16;
            ldsm2(Bh[bt], fh_b + off);
            ldsm2(Bl[bt], fl_b + off);
        }
        #pragma unroll
        for (int at = 0; at < 2; at++)
            #pragma unroll
            for (int bt = 0; bt < 8; bt++) {
                mma16816(acc[at][bt], Ah[at], Bh[bt]);
                mma16816(acc[at][bt], Ah[at], Bl[bt]);
                mma16816(acc[at][bt], Al[at], Bh[bt]);
            }
    }

    // epilogue: write S fp32, compute row-max partials
    float* srow = SBUF + (size_t)b * NN * NN;
    const int g = lane >> 2, q = (lane & 3) * 2;
    #pragma unroll
    for (int at = 0; at < 2; at++) {
        int n_lo = n0 + nw * 32 + at * 16 + g;
        int n_hi = n_lo + 8;
        float mx0 = -3.0e38f, mx1 = -3.0e38f;
        #pragma unroll
        for (int bt = 0; bt < 8; bt++) {
            int m = m0 + mw * 64 + bt * 8 + q;
            *(float2*)&srow[(size_t)n_lo * NN + m] = make_float2(acc[at][bt][0], acc[at][bt][1]);
            *(float2*)&srow[(size_t)n_hi * NN + m] = make_float2(acc[at][bt][2], acc[at][bt][3]);
            mx0 = fmaxf(mx0, fmaxf(acc[at][bt][0], acc[at][bt][1]));
            mx1 = fmaxf(mx1, fmaxf(acc[at][bt][2], acc[at][bt][3]));
        }
        mx0 = fmaxf(mx0, __shfl_xor_sync(0xffffffffu, mx0, 1));
        mx0 = fmaxf(mx0, __shfl_xor_sync(0xffffffffu, mx0, 2));
        mx1 = fmaxf(mx1, __shfl_xor_sync(0xffffffffu, mx1, 1));
        mx1 = fmaxf(mx1, __shfl_xor_sync(0xffffffffu, mx1, 2));
        if ((lane & 3) == 0) {
            int col = blockIdx.x * 2 + mw;
            PMAX[((size_t)b * NN + n_lo) * 64 + col] = mx0;
            PMAX[((size_t)b * NN + n_hi) * 64 + col] = mx1;
        }
    }
}

// ---------------------------------------------------------------------------
// K3a: row max over 64 partials
// ---------------------------------------------------------------------------
__global__ __launch_bounds__(256) void reduce_max_kernel()
{
    int r = blockIdx.x * 8 + (threadIdx.x >> 5);
    int lane = threadIdx.x & 31;
    const float* pm = PMAX + (size_t)r * 64;
    float M = fmaxf(pm[lane], pm[lane + 32]);
    #pragma unroll
    for (int off = 16; off; off >>= 1)
        M = fmaxf(M, __shfl_xor_sync(0xffffffffu, M, off));
    if (lane == 0) ROWM[r] = M;
}

// ---------------------------------------------------------------------------
// K3b: e = exp(S - M) -> transposed bf16 hi (unnormalized) + sum partials
// ---------------------------------------------------------------------------
__global__ __launch_bounds__(256) void softmax_t_kernel()
{
    __shared__ float ts[64][65];
    const int b  = blockIdx.z;
    const int n0 = blockIdx.y * 64;
    const int m0 = blockIdx.x * 64;
    const int t  = threadIdx.x;

    // read side: 4 threads per n-row, coalesced along m; also sum partials
    {
        int nl = t >> 2, ms = (t & 3) * 16;
        size_t rown = (size_t)b * NN + n0 + nl;
        float M = __ldg(&ROWM[rown]);
        const float* srow = SBUF + rown * NN + m0 + ms;
        float psum = 0.f;
        #pragma unroll
        for (int i = 0; i < 4; i++) {
            float4 v = *(const float4*)(srow + i * 4);
            float e0 = __expf(v.x - M), e1 = __expf(v.y - M);
            float e2 = __expf(v.z - M), e3 = __expf(v.w - M);
            ts[nl][ms + i * 4 + 0] = e0;
            ts[nl][ms + i * 4 + 1] = e1;
            ts[nl][ms + i * 4 + 2] = e2;
            ts[nl][ms + i * 4 + 3] = e3;
            psum += (e0 + e1) + (e2 + e3);
        }
        psum += __shfl_xor_sync(0xffffffffu, psum, 1);
        psum += __shfl_xor_sync(0xffffffffu, psum, 2);
        if ((t & 3) == 0) PSUM[rown * 64 + blockIdx.x] = psum;
    }
    __syncthreads();

    // write side: transposed, coalesced along n
    {
        int w = t >> 5, l = t & 31;
        int ml = w * 8 + (l >> 2);
        int ns = (l & 3) * 16;
        __nv_bfloat16 hi[16];
        #pragma unroll
        for (int i = 0; i < 16; i++)
            hi[i] = __float2bfloat16(ts[ns + i][ml]);
        size_t dst = ((size_t)b * NN + m0 + ml) * NN + n0 + ns;
        *(uint4*)&PTH[dst]     = ((uint4*)hi)[0];
        *(uint4*)&PTH[dst + 8] = ((uint4*)hi)[1];
    }
}

// ---------------------------------------------------------------------------
// K3c: ROWI = 1 / sum of 64 partials
// ---------------------------------------------------------------------------
__global__ __launch_bounds__(256) void reduce_sum_kernel()
{
    int r = blockIdx.x * 8 + (threadIdx.x >> 5);
    int lane = threadIdx.x & 31;
    const float* ps = PSUM + (size_t)r * 64;
    float z = ps[lane] + ps[lane + 32];
    #pragma unroll
    for (int off = 16; off; off >>= 1)
        z += __shfl_xor_sync(0xffffffffu, z, off);
    if (lane == 0) ROWI[r] = 1.f / z;
}

// ---------------------------------------------------------------------------
// K3d: h'[b,c,n] = HF[b,c,n] * ROWI[b,n] -> bf16 hi/lo
// ---------------------------------------------------------------------------
__global__ __launch_bounds__(256) void scale_h_kernel()
{
    const int b = blockIdx.x / CPAD;
    const int c = blockIdx.x % CPAD;
    const float* hrow = HF + ((size_t)b * CPAD + c) * NN;
    const float* zrow = ROWI + (size_t)b * NN;
    __nv_bfloat16* dh = HHB + ((size_t)b * CPAD + c) * NN;
    __nv_bfloat16* dl = HLB + ((size_t)b * CPAD + c) * NN;

    for (int i = threadIdx.x; i < NN / 4; i += 256) {
        float4 h = *(const float4*)&hrow[i * 4];
        float4 z = *(const float4*)&zrow[i * 4];
        float v[4] = {h.x * z.x, h.y * z.y, h.z * z.z, h.w * z.w};
        __nv_bfloat16 hi[4], lo[4];
        #pragma unroll
        for (int k = 0; k < 4; k++) {
            hi[k] = __float2bfloat16(v[k]);
            lo[k] = __float2bfloat16(v[k] - __bfloat162float(hi[k]));
        }
        *(uint2*)&dh[i * 4] = *(uint2*)hi;
        *(uint2*)&dl[i * 4] = *(uint2*)lo;
    }
}

// ---------------------------------------------------------------------------
// K4: mma.sync GEMM (2 passes: Ah*B + Al*B).  D[c(144), m(128)] = H'[c,:]e[:,m]
// out = gamma * D + x.  Grid (32, 8), 256 threads (8 warps: 2 c x 4 m).
// ---------------------------------------------------------------------------
#define KB 64
#define ST_AH 0
#define ST_AL 18432
#define ST_BH 36864
#define ST_BYTES 53248
#define SMEM_DYN (2 * ST_BYTES + 128)

__global__ __launch_bounds__(256, 1) void gemm_o_mma_kernel(
    const float* __restrict__ x, const float* __restrict__ gamma,
    float* __restrict__ out)
{
    extern __shared__ char smem_raw[];
    const uint32_t sb = (smem_u32(smem_raw) + 127) & ~127u;

    const int tid  = threadIdx.x;
    const int w    = tid >> 5;
    const int lane = tid & 31;
    const int cw   = w >> 2;           // 0 or 1
    const int mw   = w & 3;            // 0..3
    const int nct  = (cw == 0) ? 5 : 4; // c-tiles per warp (5/4 split of 9)
    const int b    = blockIdx.y;
    const int m0   = blockIdx.x * 128;

    const size_t abase = (size_t)b * CPAD;       // H' rows (c)
    const size_t bbase = (size_t)b * NN + m0;    // e^T rows (m)

    auto load_stage = [&](int st, int nk) {
        uint32_t base = sb + st * ST_BYTES;
        // A: H' hi/lo, 144 rows x 8 16B-chunks, x2 buffers = 2304
        for (int t = tid; t < 2304; t += 256) {
            int buf = t >= 1152;
            int idx = t - (buf ? 1152 : 0);
            int row = idx >> 3, q = idx & 7;
            const __nv_bfloat16* src =
                (buf ? HLB : HHB) + ((abase + row) << 12) + nk + q * 8;
            cpa16(base + (buf ? ST_AL : ST_AH) + row * 128 + ((q ^ (row & 7)) << 4), src);
        }
        // B: e^T hi only, 128 rows x 8 chunks = 1024
        for (int t = tid; t < 1024; t += 256) {
            int row = t >> 3, q = t & 7;
            const __nv_bfloat16* src = PTH + ((bbase + row) << 12) + nk + q * 8;
            cpa16(base + ST_BH + row * 128 + ((q ^ (row & 7)) << 4), src);
        }
    };

    float acc[5][4][4] = {};

    load_stage(0, 0);
    CP_COMMIT();

    const int a_roff = ((lane >> 3) & 1) * 8 + (lane & 7);
    const int a_koff = lane >> 4;
    const int bl     = lane & 15;
    const int b_roff = bl & 7;
    const int b_koff = bl >> 3;

    for (int chunk = 0; chunk < NN / KB; chunk++) {
        int cur = chunk & 1;
        if (chunk + 1 < NN / KB) {
            load_stage(cur ^ 1, (chunk + 1) * KB);
            CP_COMMIT();
            CP_WAIT1();
        } else {
            CP_WAIT0();
        }
        __syncthreads();

        uint32_t base = sb + cur * ST_BYTES;
        #pragma unroll
        for (int ks = 0; ks < 4; ks++) {
            uint32_t Ah[5][4], Al[5][4], Bh[4][2];
            #pragma unroll
            for (int ct = 0; ct < 5; ct++) {
                if (ct < nct) {
                    int row = cw * 80 + ct * 16 + a_roff;
                    int kch = ks * 2 + a_koff;
                    uint32_t off = row * 128 + ((kch ^ (row & 7)) << 4);
                    ldsm4(Ah[ct], base + ST_AH + off);
                    ldsm4(Al[ct], base + ST_AL + off);
                }
            }
            #pragma unroll
            for (int mt = 0; mt < 4; mt++) {
                int row = mw * 32 + mt * 8 + b_roff;
                int kch = ks * 2 + b_koff;
                uint32_t off = row * 128 + ((kch ^ (row & 7)) << 4);
                ldsm2(Bh[mt], base + ST_BH + off);
            }
            #pragma unroll
            for (int ct = 0; ct < 5; ct++) {
                if (ct < nct) {
                    #pragma unroll
                    for (int mt = 0; mt < 4; mt++) {
                        mma16816(acc[ct][mt], Ah[ct], Bh[mt]);
                        mma16816(acc[ct][mt], Al[ct], Bh[mt]);
                    }
                }
            }
        }
        __syncthreads();
    }

    // ---- epilogue: out = gamma*D + x ----
    const float gm = __ldg(gamma);
    const int g = lane >> 2;
    const int mo = (lane & 3) * 2;
    #pragma unroll
    for (int ct = 0; ct < 5; ct++) {
        if (ct >= nct) break;
        int c0 = cw * 80 + ct * 16 + g;
        #pragma unroll
        for (int mt = 0; mt < 4; mt++) {
            int m = m0 + mw * 32 + mt * 8 + mo;
            if (c0 < CC) {
                size_t idx = ((size_t)b * CC + c0) * NN + m;
                float2 xv = *(const float2*)&x[idx];
                *(float2*)&out[idx] = make_float2(gm * acc[ct][mt][0] + xv.x,
                                                  gm * acc[ct][mt][1] + xv.y);
            }
            if (c0 + 8 < CC) {
                size_t idx = ((size_t)b * CC + c0 + 8) * NN + m;
                float2 xv = *(const float2*)&x[idx];
                *(float2*)&out[idx] = make_float2(gm * acc[ct][mt][2] + xv.x,
                                                  gm * acc[ct][mt][3] + xv.y);
            }
        }
    }
}

// ---------------------------------------------------------------------------
extern "C" void kernel_launch(void* const* d_in, const int* in_sizes, int n_in,
                              void* d_out, int out_size)
{
    const float* x   = (const float*)d_in[0];
    const float* wF  = (const float*)d_in[1];
    const float* bF  = (const float*)d_in[2];
    const float* fw  = (const float*)d_in[3];
    const float* fbe = (const float*)d_in[4];
    const float* fm  = (const float*)d_in[5];
    const float* fv  = (const float*)d_in[6];
    const float* wG  = (const float*)d_in[7];
    const float* bG  = (const float*)d_in[8];
    const float* gw  = (const float*)d_in[9];
    const float* gbe = (const float*)d_in[10];
    const float* gm  = (const float*)d_in[11];
    const float* gv  = (const float*)d_in[12];
    const float* wH  = (const float*)d_in[13];
    const float* bH  = (const float*)d_in[14];
    const float* hw  = (const float*)d_in[15];
    const float* hbe = (const float*)d_in[16];
    const float* hm  = (const float*)d_in[17];
    const float* hv  = (const float*)d_in[18];
    const float* gamma = (const float*)d_in[19];
    float* out = (float*)d_out;

    cudaFuncSetAttribute(gemm_o_mma_kernel,
                         cudaFuncAttributeMaxDynamicSharedMemorySize, SMEM_DYN);

    proj_kernel<<<dim3(NN / 64, BB), 256>>>(x,
        wF, bF, fw, fbe, fm, fv,
        wG, bG, gw, gbe, gm, gv,
        wH, bH, hw, hbe, hm, hv);
    gemm_s_mma_kernel<<<dim3(NN / 128, NN / 128, BB), 256>>>();
    reduce_max_kernel<<<BB * NN / 8, 256>>>();
    softmax_t_kernel<<<dim3(NN / 64, NN / 64, BB), 256>>>();
    reduce_sum_kernel<<<BB * NN / 8, 256>>>();
    scale_h_kernel<<<BB * CPAD, 256>>>();
    gemm_o_mma_kernel<<<dim3(NN / 128, BB), 256, SMEM_DYN>>>(x, gamma, out);
}

// round 5
// speedup vs baseline: 2.5703x; 1.2871x over previous
#include <cuda_runtime.h>
#include <cuda_bf16.h>
#include <cstdint>

#define BB 8
#define CC 130
#define CPAD 144          // c padded to 9 x 16 for MMA M tiles
#define CQ 32
#define NN 4096
#define BN_EPS 1e-5f

// ---------------- static device scratch ----------------
__device__ float FBUF[BB * CQ * NN];
__device__ float GBUF[BB * CQ * NN];
__device__ float HF[(size_t)BB * CPAD * NN];            // h fp32 (pre-scale)
__device__ __nv_bfloat16 HHB[(size_t)BB * CPAD * NN];   // h' = h*invZ (bf16)
__device__ __nv_bfloat16 PTH[(size_t)BB * NN * NN];     // e^T: [b][m][n] bf16
__device__ float PMAX[(size_t)BB * NN * 64];
__device__ float PSUM[(size_t)BB * NN * 64];
__device__ float ROWM[BB * NN];
__device__ float ROWI[BB * NN];

// ---------------- helpers ----------------
__device__ __forceinline__ uint32_t smem_u32(const void* p) {
    uint32_t a;
    asm("{ .reg .u64 t; cvta.to.shared.u64 t, %1; cvt.u32.u64 %0, t; }" : "=r"(a) : "l"(p));
    return a;
}
__device__ __forceinline__ void cpa16(uint32_t dst, const void* src) {
    asm volatile("cp.async.cg.shared.global [%0], [%1], 16;" :: "r"(dst), "l"(src));
}
#define CP_COMMIT() asm volatile("cp.async.commit_group;" ::: "memory")
#define CP_WAIT1()  asm volatile("cp.async.wait_group 1;" ::: "memory")
#define CP_WAIT0()  asm volatile("cp.async.wait_group 0;" ::: "memory")

__device__ __forceinline__ void ldsm4(uint32_t* r, uint32_t addr) {
    asm volatile("ldmatrix.sync.aligned.m8n8.x4.shared.b16 {%0,%1,%2,%3}, [%4];"
                 : "=r"(r[0]), "=r"(r[1]), "=r"(r[2]), "=r"(r[3]) : "r"(addr));
}
__device__ __forceinline__ void ldsm2(uint32_t* r, uint32_t addr) {
    asm volatile("ldmatrix.sync.aligned.m8n8.x2.shared.b16 {%0,%1}, [%2];"
                 : "=r"(r[0]), "=r"(r[1]) : "r"(addr));
}
__device__ __forceinline__ void mma16816(float* d, const uint32_t* a, const uint32_t* b) {
    asm volatile("mma.sync.aligned.m16n8k16.row.col.f32.bf16.bf16.f32 "
                 "{%0,%1,%2,%3}, {%4,%5,%6,%7}, {%8,%9}, {%0,%1,%2,%3};"
                 : "+f"(d[0]), "+f"(d[1]), "+f"(d[2]), "+f"(d[3])
                 : "r"(a[0]), "r"(a[1]), "r"(a[2]), "r"(a[3]), "r"(b[0]), "r"(b[1]));
}

// ---------------------------------------------------------------------------
// K1: fused 1x1-conv + BN + ReLU. F,G -> fp32; H -> fp32 HF (+ zero pad rows)
// ---------------------------------------------------------------------------
__global__ __launch_bounds__(256) void proj_kernel(
    const float* __restrict__ x,
    const float* __restrict__ wF, const float* __restrict__ bF,
    const float* __restrict__ fw, const float* __restrict__ fbe,
    const float* __restrict__ fm, const float* __restrict__ fv,
    const float* __restrict__ wG, const float* __restrict__ bG,
    const float* __restrict__ gw, const float* __restrict__ gbe,
    const float* __restrict__ gm, const float* __restrict__ gv,
    const float* __restrict__ wH, const float* __restrict__ bH,
    const float* __restrict__ hw, const float* __restrict__ hbe,
    const float* __restrict__ hm, const float* __restrict__ hv)
{
    __shared__ float xs[CC][64];
    const int b  = blockIdx.y;
    const int n0 = blockIdx.x * 64;
    const int tid = threadIdx.x;

    for (int idx = tid; idx < CC * 64; idx += 256) {
        int c = idx >> 6, i = idx & 63;
        xs[c][i] = x[((size_t)b * CC + c) * NN + n0 + i];
    }
    __syncthreads();

    const int tx = tid & 15;
    const int ty = tid >> 4;

    for (int o = ty; o < 2 * CQ + CPAD; o += 16) {
        if (o >= 2 * CQ + CC) {
            int oo = o - 2 * CQ;    // pad rows [130,144): zero
            *(float4*)&HF[((size_t)b * CPAD + oo) * NN + n0 + tx * 4] =
                make_float4(0.f, 0.f, 0.f, 0.f);
            continue;
        }
        const float* wrow;
        const float *pb, *pw, *pbe, *pm, *pv;
        int oo, which;
        if (o < CQ)          { oo = o;          which = 0; wrow = wF + oo * CC; pb = bF; pw = fw; pbe = fbe; pm = fm; pv = fv; }
        else if (o < 2 * CQ) { oo = o - CQ;     which = 1; wrow = wG + oo * CC; pb = bG; pw = gw; pbe = gbe; pm = gm; pv = gv; }
        else                 { oo = o - 2 * CQ; which = 2; wrow = wH + oo * CC; pb = bH; pw = hw; pbe = hbe; pm = hm; pv = hv; }

        float a0 = 0.f, a1 = 0.f, a2 = 0.f, a3 = 0.f;
        #pragma unroll 2
        for (int c = 0; c < CC; c++) {
            float wv = __ldg(wrow + c);
            float4 xv = *(const float4*)&xs[c][tx * 4];
            a0 += wv * xv.x; a1 += wv * xv.y; a2 += wv * xv.z; a3 += wv * xv.w;
        }
        float scale = __ldg(pw + oo) * rsqrtf(__ldg(pv + oo) + BN_EPS);
        float bias  = __ldg(pb + oo) - __ldg(pm + oo);
        float be    = __ldg(pbe + oo);
        float4 r;
        r.x = fmaxf(scale * (a0 + bias) + be, 0.f);
        r.y = fmaxf(scale * (a1 + bias) + be, 0.f);
        r.z = fmaxf(scale * (a2 + bias) + be, 0.f);
        r.w = fmaxf(scale * (a3 + bias) + be, 0.f);
        if (which == 2) {
            *(float4*)&HF[((size_t)b * CPAD + oo) * NN + n0 + tx * 4] = r;
        } else {
            float* dst = (which == 0 ? FBUF : GBUF) + ((size_t)b * CQ + oo) * NN;
            *(float4*)&dst[n0 + tx * 4] = r;
        }
    }
}

// ---------------------------------------------------------------------------
// K2a: max pass — recompute S hi-only on tensor cores, emit only max partials.
// Grid: (32 m-tiles, 32 n-tiles, 8). 8 warps (4n x 2m).
// ---------------------------------------------------------------------------
__global__ __launch_bounds__(256) void smax_kernel()
{
    __shared__ __align__(16) __nv_bfloat16 gh[128][40];
    __shared__ __align__(16) __nv_bfloat16 fh[128][40];

    const int b  = blockIdx.z;
    const int m0 = blockIdx.x * 128;
    const int n0 = blockIdx.y * 128;
    const int tid = threadIdx.x;

    for (int idx = tid; idx < CQ * 128; idx += 256) {
        int c = idx >> 7, i = idx & 127;
        gh[i][c] = __float2bfloat16(GBUF[((size_t)b * CQ + c) * NN + n0 + i]);
        fh[i][c] = __float2bfloat16(FBUF[((size_t)b * CQ + c) * NN + m0 + i]);
    }
    __syncthreads();

    const int w = tid >> 5, lane = tid & 31;
    const int nw = w >> 1, mw = w & 1;
    const int a_roff = ((lane >> 3) & 1) * 8 + (lane & 7);
    const int a_koff = lane >> 4;
    const int bl = lane & 15;
    const int b_roff = bl & 7, b_koff = bl >> 3;

    const uint32_t gh_b = smem_u32(gh), fh_b = smem_u32(fh);

    float acc[2][8][4] = {};
    #pragma unroll
    for (int ks = 0; ks < 2; ks++) {
        uint32_t Ah[2][4], Bh[8][2];
        #pragma unroll
        for (int at = 0; at < 2; at++) {
            int row = nw * 32 + at * 16 + a_roff;
            ldsm4(Ah[at], gh_b + row * 80 + ks * 32 + a_koff * 16);
        }
        #pragma unroll
        for (int bt = 0; bt < 8; bt++) {
            int row = mw * 64 + bt * 8 + b_roff;
            ldsm2(Bh[bt], fh_b + row * 80 + ks * 32 + b_koff * 16);
        }
        #pragma unroll
        for (int at = 0; at < 2; at++)
            #pragma unroll
            for (int bt = 0; bt < 8; bt++)
                mma16816(acc[at][bt], Ah[at], Bh[bt]);
    }

    const int g = lane >> 2;
    #pragma unroll
    for (int at = 0; at < 2; at++) {
        int n_lo = n0 + nw * 32 + at * 16 + g;
        int n_hi = n_lo + 8;
        float mx0 = -3.0e38f, mx1 = -3.0e38f;
        #pragma unroll
        for (int bt = 0; bt < 8; bt++) {
            mx0 = fmaxf(mx0, fmaxf(acc[at][bt][0], acc[at][bt][1]));
            mx1 = fmaxf(mx1, fmaxf(acc[at][bt][2], acc[at][bt][3]));
        }
        mx0 = fmaxf(mx0, __shfl_xor_sync(0xffffffffu, mx0, 1));
        mx0 = fmaxf(mx0, __shfl_xor_sync(0xffffffffu, mx0, 2));
        mx1 = fmaxf(mx1, __shfl_xor_sync(0xffffffffu, mx1, 1));
        mx1 = fmaxf(mx1, __shfl_xor_sync(0xffffffffu, mx1, 2));
        if ((lane & 3) == 0) {
            int col = blockIdx.x * 2 + mw;
            PMAX[((size_t)b * NN + n_lo) * 64 + col] = mx0;
            PMAX[((size_t)b * NN + n_hi) * 64 + col] = mx1;
        }
    }
}

// ---------------------------------------------------------------------------
// K2b: reduce row max over 64 partials
// ---------------------------------------------------------------------------
__global__ __launch_bounds__(256) void reduce_max_kernel()
{
    int r = blockIdx.x * 8 + (threadIdx.x >> 5);
    int lane = threadIdx.x & 31;
    const float* pm = PMAX + (size_t)r * 64;
    float M = fmaxf(pm[lane], pm[lane + 32]);
    #pragma unroll
    for (int off = 16; off; off >>= 1)
        M = fmaxf(M, __shfl_xor_sync(0xffffffffu, M, off));
    if (lane == 0) ROWM[r] = M;
}

// ---------------------------------------------------------------------------
// K2c: recompute S (bf16x3), e = exp(S - M) -> PTH (bf16, transposed via smem)
//      + per-(row, m-warp-half) sum partials into PSUM[.., 64].
// Dynamic smem: tiles (40960 B) then reused (aliased) as esm [128][136] bf16.
// ---------------------------------------------------------------------------
#define PE 136
#define SE_SMEM 40960

__global__ __launch_bounds__(256) void gemm_se_kernel()
{
    extern __shared__ char dyn[];
    __nv_bfloat16 (*gh)[40] = (__nv_bfloat16(*)[40])(dyn);
    __nv_bfloat16 (*gl)[40] = (__nv_bfloat16(*)[40])(dyn + 10240);
    __nv_bfloat16 (*fh)[40] = (__nv_bfloat16(*)[40])(dyn + 20480);
    __nv_bfloat16 (*fl)[40] = (__nv_bfloat16(*)[40])(dyn + 30720);
    __nv_bfloat16* esm = (__nv_bfloat16*)dyn;   // aliases tiles (used after)

    const int b  = blockIdx.z;
    const int m0 = blockIdx.x * 128;
    const int n0 = blockIdx.y * 128;
    const int tid = threadIdx.x;

    for (int idx = tid; idx < CQ * 128; idx += 256) {
        int c = idx >> 7, i = idx & 127;
        float gv = GBUF[((size_t)b * CQ + c) * NN + n0 + i];
        float fv = FBUF[((size_t)b * CQ + c) * NN + m0 + i];
        __nv_bfloat16 h1 = __float2bfloat16(gv);
        gh[i][c] = h1;
        gl[i][c] = __float2bfloat16(gv - __bfloat162float(h1));
        __nv_bfloat16 h2 = __float2bfloat16(fv);
        fh[i][c] = h2;
        fl[i][c] = __float2bfloat16(fv - __bfloat162float(h2));
    }
    __syncthreads();

    const int w = tid >> 5, lane = tid & 31;
    const int nw = w >> 1, mw = w & 1;
    const int a_roff = ((lane >> 3) & 1) * 8 + (lane & 7);
    const int a_koff = lane >> 4;
    const int bl = lane & 15;
    const int b_roff = bl & 7, b_koff = bl >> 3;

    const uint32_t gh_b = smem_u32(gh), gl_b = smem_u32(gl);
    const uint32_t fh_b = smem_u32(fh), fl_b = smem_u32(fl);

    float acc[2][8][4] = {};
    #pragma unroll
    for (int ks = 0; ks < 2; ks++) {
        uint32_t Ah[2][4], Al[2][4], Bh[8][2], Bl[8][2];
        #pragma unroll
        for (int at = 0; at < 2; at++) {
            int row = nw * 32 + at * 16 + a_roff;
            uint32_t off = row * 80 + ks * 32 + a_koff * 16;
            ldsm4(Ah[at], gh_b + off);
            ldsm4(Al[at], gl_b + off);
        }
        #pragma unroll
        for (int bt = 0; bt < 8; bt++) {
            int row = mw * 64 + bt * 8 + b_roff;
            uint32_t off = row * 80 + ks * 32 + b_koff * 16;
            ldsm2(Bh[bt], fh_b + off);
            ldsm2(Bl[bt], fl_b + off);
        }
        #pragma unroll
        for (int at = 0; at < 2; at++)
            #pragma unroll
            for (int bt = 0; bt < 8; bt++) {
                mma16816(acc[at][bt], Ah[at], Bh[bt]);
                mma16816(acc[at][bt], Ah[at], Bl[bt]);
                mma16816(acc[at][bt], Al[at], Bh[bt]);
            }
    }
    __syncthreads();   // all ldsm done before esm overwrites tiles

    // exp + store to esm[m][n] (local), accumulate row-sum partials
    const int g = lane >> 2, q = (lane & 3) * 2;
    #pragma unroll
    for (int at = 0; at < 2; at++) {
        int nl_lo = nw * 32 + at * 16 + g;
        int nl_hi = nl_lo + 8;
        float Mlo = __ldg(&ROWM[(size_t)b * NN + n0 + nl_lo]);
        float Mhi = __ldg(&ROWM[(size_t)b * NN + n0 + nl_hi]);
        float s_lo = 0.f, s_hi = 0.f;
        #pragma unroll
        for (int bt = 0; bt < 8; bt++) {
            int ml = mw * 64 + bt * 8 + q;
            float e0 = __expf(acc[at][bt][0] - Mlo);
            float e1 = __expf(acc[at][bt][1] - Mlo);
            float e2 = __expf(acc[at][bt][2] - Mhi);
            float e3 = __expf(acc[at][bt][3] - Mhi);
            esm[(ml    ) * PE + nl_lo] = __float2bfloat16(e0);
            esm[(ml + 1) * PE + nl_lo] = __float2bfloat16(e1);
            esm[(ml    ) * PE + nl_hi] = __float2bfloat16(e2);
            esm[(ml + 1) * PE + nl_hi] = __float2bfloat16(e3);
            s_lo += e0 + e1;
            s_hi += e2 + e3;
        }
        s_lo += __shfl_xor_sync(0xffffffffu, s_lo, 1);
        s_lo += __shfl_xor_sync(0xffffffffu, s_lo, 2);
        s_hi += __shfl_xor_sync(0xffffffffu, s_hi, 1);
        s_hi += __shfl_xor_sync(0xffffffffu, s_hi, 2);
        if ((lane & 3) == 0) {
            int col = blockIdx.x * 2 + mw;
            PSUM[((size_t)b * NN + n0 + nl_lo) * 64 + col] = s_lo;
            PSUM[((size_t)b * NN + n0 + nl_hi) * 64 + col] = s_hi;
        }
    }
    __syncthreads();

    // write out coalesced: warp handles 2 m-rows per iter, 16 lanes per row
    const int nch = lane & 15;
    #pragma unroll
    for (int it = 0; it < 8; it++) {
        int ml = it * 16 + w * 2 + (lane >> 4);
        uint4 v = *(const uint4*)&esm[ml * PE + nch * 8];
        size_t dst = ((size_t)b * NN + m0 + ml) * NN + n0 + nch * 8;
        *(uint4*)&PTH[dst] = v;
    }
}

// ---------------------------------------------------------------------------
// K2d: ROWI = 1 / sum of 64 partials
// ---------------------------------------------------------------------------
__global__ __launch_bounds__(256) void reduce_sum_kernel()
{
    int r = blockIdx.x * 8 + (threadIdx.x >> 5);
    int lane = threadIdx.x & 31;
    const float* ps = PSUM + (size_t)r * 64;
    float z = ps[lane] + ps[lane + 32];
    #pragma unroll
    for (int off = 16; off; off >>= 1)
        z += __shfl_xor_sync(0xffffffffu, z, off);
    if (lane == 0) ROWI[r] = 1.f / z;
}

// ---------------------------------------------------------------------------
// K3: h'[b,c,n] = HF[b,c,n] * ROWI[b,n] -> bf16
// ---------------------------------------------------------------------------
__global__ __launch_bounds__(256) void scale_h_kernel()
{
    const int b = blockIdx.x / CPAD;
    const int c = blockIdx.x % CPAD;
    const float* hrow = HF + ((size_t)b * CPAD + c) * NN;
    const float* zrow = ROWI + (size_t)b * NN;
    __nv_bfloat16* dh = HHB + ((size_t)b * CPAD + c) * NN;

    for (int i = threadIdx.x; i < NN / 4; i += 256) {
        float4 h = *(const float4*)&hrow[i * 4];
        float4 z = *(const float4*)&zrow[i * 4];
        __nv_bfloat16 hi[4];
        hi[0] = __float2bfloat16(h.x * z.x);
        hi[1] = __float2bfloat16(h.y * z.y);
        hi[2] = __float2bfloat16(h.z * z.z);
        hi[3] = __float2bfloat16(h.w * z.w);
        *(uint2*)&dh[i * 4] = *(uint2*)hi;
    }
}

// ---------------------------------------------------------------------------
// K4: mma.sync GEMM (single pass).  D[c(144), m(128)] = H'[c,:] e[:,m]
// out = gamma * D + x.  Grid (32, 8), 256 threads (8 warps: 2 c x 4 m).
// ---------------------------------------------------------------------------
#define KB 64
#define ST_AH 0
#define ST_BH 18432
#define ST_BYTES 34816
#define SMEM_DYN (2 * ST_BYTES + 128)

__global__ __launch_bounds__(256, 1) void gemm_o_mma_kernel(
    const float* __restrict__ x, const float* __restrict__ gamma,
    float* __restrict__ out)
{
    extern __shared__ char smem_raw[];
    const uint32_t sb = (smem_u32(smem_raw) + 127) & ~127u;

    const int tid  = threadIdx.x;
    const int w    = tid >> 5;
    const int lane = tid & 31;
    const int cw   = w >> 2;           // 0 or 1
    const int mw   = w & 3;            // 0..3
    const int nct  = (cw == 0) ? 5 : 4; // c-tiles per warp (5/4 split of 9)
    const int b    = blockIdx.y;
    const int m0   = blockIdx.x * 128;

    const size_t abase = (size_t)b * CPAD;       // H' rows (c)
    const size_t bbase = (size_t)b * NN + m0;    // e^T rows (m)

    auto load_stage = [&](int st, int nk) {
        uint32_t base = sb + st * ST_BYTES;
        // A: H' hi, 144 rows x 8 16B-chunks = 1152
        for (int t = tid; t < 1152; t += 256) {
            int row = t >> 3, q = t & 7;
            const __nv_bfloat16* src = HHB + ((abase + row) << 12) + nk + q * 8;
            cpa16(base + ST_AH + row * 128 + ((q ^ (row & 7)) << 4), src);
        }
        // B: e^T, 128 rows x 8 chunks = 1024
        for (int t = tid; t < 1024; t += 256) {
            int row = t >> 3, q = t & 7;
            const __nv_bfloat16* src = PTH + ((bbase + row) << 12) + nk + q * 8;
            cpa16(base + ST_BH + row * 128 + ((q ^ (row & 7)) << 4), src);
        }
    };

    float acc[5][4][4] = {};

    load_stage(0, 0);
    CP_COMMIT();

    const int a_roff = ((lane >> 3) & 1) * 8 + (lane & 7);
    const int a_koff = lane >> 4;
    const int bl     = lane & 15;
    const int b_roff = bl & 7;
    const int b_koff = bl >> 3;

    for (int chunk = 0; chunk < NN / KB; chunk++) {
        int cur = chunk & 1;
        if (chunk + 1 < NN / KB) {
            load_stage(cur ^ 1, (chunk + 1) * KB);
            CP_COMMIT();
            CP_WAIT1();
        } else {
            CP_WAIT0();
        }
        __syncthreads();

        uint32_t base = sb + cur * ST_BYTES;
        #pragma unroll
        for (int ks = 0; ks < 4; ks++) {
            uint32_t Ah[5][4], Bh[4][2];
            #pragma unroll
            for (int ct = 0; ct < 5; ct++) {
                if (ct < nct) {
                    int row = cw * 80 + ct * 16 + a_roff;
                    int kch = ks * 2 + a_koff;
                    ldsm4(Ah[ct], base + ST_AH + row * 128 + ((kch ^ (row & 7)) << 4));
                }
            }
            #pragma unroll
            for (int mt = 0; mt < 4; mt++) {
                int row = mw * 32 + mt * 8 + b_roff;
                int kch = ks * 2 + b_koff;
                ldsm2(Bh[mt], base + ST_BH + row * 128 + ((kch ^ (row & 7)) << 4));
            }
            #pragma unroll
            for (int ct = 0; ct < 5; ct++) {
                if (ct < nct) {
                    #pragma unroll
                    for (int mt = 0; mt < 4; mt++)
                        mma16816(acc[ct][mt], Ah[ct], Bh[mt]);
                }
            }
        }
        __syncthreads();
    }

    // ---- epilogue: out = gamma*D + x ----
    const float gm = __ldg(gamma);
    const int g = lane >> 2;
    const int mo = (lane & 3) * 2;
    #pragma unroll
    for (int ct = 0; ct < 5; ct++) {
        if (ct >= nct) break;
        int c0 = cw * 80 + ct * 16 + g;
        #pragma unroll
        for (int mt = 0; mt < 4; mt++) {
            int m = m0 + mw * 32 + mt * 8 + mo;
            if (c0 < CC) {
                size_t idx = ((size_t)b * CC + c0) * NN + m;
                float2 xv = *(const float2*)&x[idx];
                *(float2*)&out[idx] = make_float2(gm * acc[ct][mt][0] + xv.x,
                                                  gm * acc[ct][mt][1] + xv.y);
            }
            if (c0 + 8 < CC) {
                size_t idx = ((size_t)b * CC + c0 + 8) * NN + m;
                float2 xv = *(const float2*)&x[idx];
                *(float2*)&out[idx] = make_float2(gm * acc[ct][mt][2] + xv.x,
                                                  gm * acc[ct][mt][3] + xv.y);
            }
        }
    }
}

// ---------------------------------------------------------------------------
extern "C" void kernel_launch(void* const* d_in, const int* in_sizes, int n_in,
                              void* d_out, int out_size)
{
    const float* x   = (const float*)d_in[0];
    const float* wF  = (const float*)d_in[1];
    const float* bF  = (const float*)d_in[2];
    const float* fw  = (const float*)d_in[3];
    const float* fbe = (const float*)d_in[4];
    const float* fm  = (const float*)d_in[5];
    const float* fv  = (const float*)d_in[6];
    const float* wG  = (const float*)d_in[7];
    const float* bG  = (const float*)d_in[8];
    const float* gw  = (const float*)d_in[9];
    const float* gbe = (const float*)d_in[10];
    const float* gm  = (const float*)d_in[11];
    const float* gv  = (const float*)d_in[12];
    const float* wH  = (const float*)d_in[13];
    const float* bH  = (const float*)d_in[14];
    const float* hw  = (const float*)d_in[15];
    const float* hbe = (const float*)d_in[16];
    const float* hm  = (const float*)d_in[17];
    const float* hv  = (const float*)d_in[18];
    const float* gamma = (const float*)d_in[19];
    float* out = (float*)d_out;

    cudaFuncSetAttribute(gemm_se_kernel,
                         cudaFuncAttributeMaxDynamicSharedMemorySize, SE_SMEM);
    cudaFuncSetAttribute(gemm_o_mma_kernel,
                         cudaFuncAttributeMaxDynamicSharedMemorySize, SMEM_DYN);

    proj_kernel<<<dim3(NN / 64, BB), 256>>>(x,
        wF, bF, fw, fbe, fm, fv,
        wG, bG, gw, gbe, gm, gv,
        wH, bH, hw, hbe, hm, hv);
    smax_kernel<<<dim3(NN / 128, NN / 128, BB), 256>>>();
    reduce_max_kernel<<<BB * NN / 8, 256>>>();
    gemm_se_kernel<<<dim3(NN / 128, NN / 128, BB), 256, SE_SMEM>>>();
    reduce_sum_kernel<<<BB * NN / 8, 256>>>();
    scale_h_kernel<<<BB * CPAD, 256>>>();
    gemm_o_mma_kernel<<<dim3(NN / 128, BB), 256, SMEM_DYN>>>(x, gamma, out);
}

// round 6
// speedup vs baseline: 2.6823x; 1.0436x over previous
#include <cuda_runtime.h>
#include <cuda_bf16.h>
#include <cstdint>

#define BB 8
#define CC 130
#define CPAD 144          // c padded to 9 x 16 for MMA M tiles
#define CQ 32
#define NN 4096
#define BN_EPS 1e-5f

// ---------------- static device scratch ----------------
__device__ float FBUF[BB * CQ * NN];
__device__ float GBUF[BB * CQ * NN];
__device__ float HF[(size_t)BB * CPAD * NN];            // h fp32 (pre-scale)
__device__ __nv_bfloat16 HHB[(size_t)BB * CPAD * NN];   // h' = h*invZ (bf16)
__device__ __nv_bfloat16 PTH[(size_t)BB * NN * NN];     // e^T: [b][m][n] bf16
__device__ float PSUM[(size_t)BB * NN * 128];
__device__ float GNRM[BB * NN];                          // ||g_n||
__device__ int   FMXI[BB];                               // max_m ||f_m||^2 (bits)
__device__ float ROWI[BB * NN];                          // 1/Z

// ---------------- helpers ----------------
__device__ __forceinline__ uint32_t smem_u32(const void* p) {
    uint32_t a;
    asm("{ .reg .u64 t; cvta.to.shared.u64 t, %1; cvt.u32.u64 %0, t; }" : "=r"(a) : "l"(p));
    return a;
}
__device__ __forceinline__ void cpa16(uint32_t dst, const void* src) {
    asm volatile("cp.async.cg.shared.global [%0], [%1], 16;" :: "r"(dst), "l"(src));
}
#define CP_COMMIT() asm volatile("cp.async.commit_group;" ::: "memory")
#define CP_WAIT1()  asm volatile("cp.async.wait_group 1;" ::: "memory")
#define CP_WAIT0()  asm volatile("cp.async.wait_group 0;" ::: "memory")

__device__ __forceinline__ void ldsm4(uint32_t* r, uint32_t addr) {
    asm volatile("ldmatrix.sync.aligned.m8n8.x4.shared.b16 {%0,%1,%2,%3}, [%4];"
                 : "=r"(r[0]), "=r"(r[1]), "=r"(r[2]), "=r"(r[3]) : "r"(addr));
}
__device__ __forceinline__ void ldsm2(uint32_t* r, uint32_t addr) {
    asm volatile("ldmatrix.sync.aligned.m8n8.x2.shared.b16 {%0,%1}, [%2];"
                 : "=r"(r[0]), "=r"(r[1]) : "r"(addr));
}
__device__ __forceinline__ void mma16816(float* d, const uint32_t* a, const uint32_t* b) {
    asm volatile("mma.sync.aligned.m16n8k16.row.col.f32.bf16.bf16.f32 "
                 "{%0,%1,%2,%3}, {%4,%5,%6,%7}, {%8,%9}, {%0,%1,%2,%3};"
                 : "+f"(d[0]), "+f"(d[1]), "+f"(d[2]), "+f"(d[3])
                 : "r"(a[0]), "r"(a[1]), "r"(a[2]), "r"(a[3]), "r"(b[0]), "r"(b[1]));
}

// ---------------------------------------------------------------------------
// K1: fused 1x1-conv + BN + ReLU. F,G -> fp32; H -> fp32 HF (+ zero pad rows)
// ---------------------------------------------------------------------------
__global__ __launch_bounds__(256) void proj_kernel(
    const float* __restrict__ x,
    const float* __restrict__ wF, const float* __restrict__ bF,
    const float* __restrict__ fw, const float* __restrict__ fbe,
    const float* __restrict__ fm, const float* __restrict__ fv,
    const float* __restrict__ wG, const float* __restrict__ bG,
    const float* __restrict__ gw, const float* __restrict__ gbe,
    const float* __restrict__ gm, const float* __restrict__ gv,
    const float* __restrict__ wH, const float* __restrict__ bH,
    const float* __restrict__ hw, const float* __restrict__ hbe,
    const float* __restrict__ hm, const float* __restrict__ hv)
{
    __shared__ float xs[CC][64];
    const int b  = blockIdx.y;
    const int n0 = blockIdx.x * 64;
    const int tid = threadIdx.x;

    for (int idx = tid; idx < CC * 64; idx += 256) {
        int c = idx >> 6, i = idx & 63;
        xs[c][i] = x[((size_t)b * CC + c) * NN + n0 + i];
    }
    __syncthreads();

    const int tx = tid & 15;
    const int ty = tid >> 4;

    for (int o = ty; o < 2 * CQ + CPAD; o += 16) {
        if (o >= 2 * CQ + CC) {
            int oo = o - 2 * CQ;    // pad rows [130,144): zero
            *(float4*)&HF[((size_t)b * CPAD + oo) * NN + n0 + tx * 4] =
                make_float4(0.f, 0.f, 0.f, 0.f);
            continue;
        }
        const float* wrow;
        const float *pb, *pw, *pbe, *pm, *pv;
        int oo, which;
        if (o < CQ)          { oo = o;          which = 0; wrow = wF + oo * CC; pb = bF; pw = fw; pbe = fbe; pm = fm; pv = fv; }
        else if (o < 2 * CQ) { oo = o - CQ;     which = 1; wrow = wG + oo * CC; pb = bG; pw = gw; pbe = gbe; pm = gm; pv = gv; }
        else                 { oo = o - 2 * CQ; which = 2; wrow = wH + oo * CC; pb = bH; pw = hw; pbe = hbe; pm = hm; pv = hv; }

        float a0 = 0.f, a1 = 0.f, a2 = 0.f, a3 = 0.f;
        #pragma unroll 2
        for (int c = 0; c < CC; c++) {
            float wv = __ldg(wrow + c);
            float4 xv = *(const float4*)&xs[c][tx * 4];
            a0 += wv * xv.x; a1 += wv * xv.y; a2 += wv * xv.z; a3 += wv * xv.w;
        }
        float scale = __ldg(pw + oo) * rsqrtf(__ldg(pv + oo) + BN_EPS);
        float bias  = __ldg(pb + oo) - __ldg(pm + oo);
        float be    = __ldg(pbe + oo);
        float4 r;
        r.x = fmaxf(scale * (a0 + bias) + be, 0.f);
        r.y = fmaxf(scale * (a1 + bias) + be, 0.f);
        r.z = fmaxf(scale * (a2 + bias) + be, 0.f);
        r.w = fmaxf(scale * (a3 + bias) + be, 0.f);
        if (which == 2) {
            *(float4*)&HF[((size_t)b * CPAD + oo) * NN + n0 + tx * 4] = r;
        } else {
            float* dst = (which == 0 ? FBUF : GBUF) + ((size_t)b * CQ + oo) * NN;
            *(float4*)&dst[n0 + tx * 4] = r;
        }
    }
}

// ---------------------------------------------------------------------------
// K1b: GNRM[b,n] = ||g_:,n||, FMXI[b] = max_n ||f_:,n||^2 (monotone atomicMax)
// ---------------------------------------------------------------------------
__global__ __launch_bounds__(256) void norms_kernel()
{
    const int b = blockIdx.y;
    const int n = blockIdx.x * 256 + threadIdx.x;
    float fs = 0.f, gs = 0.f;
    #pragma unroll
    for (int c = 0; c < CQ; c++) {
        float fv = FBUF[((size_t)b * CQ + c) * NN + n];
        float gv = GBUF[((size_t)b * CQ + c) * NN + n];
        fs += fv * fv;
        gs += gv * gv;
    }
    GNRM[(size_t)b * NN + n] = sqrtf(gs);
    #pragma unroll
    for (int off = 16; off; off >>= 1)
        fs = fmaxf(fs, __shfl_xor_sync(0xffffffffu, fs, off));
    if ((threadIdx.x & 31) == 0)
        atomicMax(&FMXI[b], __float_as_int(fs));   // fs >= 0: int-max == float-max
}

// ---------------------------------------------------------------------------
// K2: recompute S (bf16x3), e = exp(S - M~) -> PTH (bf16, transposed via smem)
//     + per-(row, 32-m) sum partials into PSUM[.., 128].
// Block: 64n x 128m; 8 warps (2n x 4m). M~[n] = GNRM[n]*sqrt(FMXI[b]) >= max s.
// Dyn smem: tiles (30720 B: gh,gl 64x40; fh,fl 128x40) aliased by esm[128][72].
// ---------------------------------------------------------------------------
#define PE 72
#define SE_SMEM 30720

__global__ __launch_bounds__(256, 3) void gemm_se_kernel()
{
    extern __shared__ char dyn[];
    __nv_bfloat16 (*gh)[40] = (__nv_bfloat16(*)[40])(dyn);
    __nv_bfloat16 (*gl)[40] = (__nv_bfloat16(*)[40])(dyn + 5120);
    __nv_bfloat16 (*fh)[40] = (__nv_bfloat16(*)[40])(dyn + 10240);
    __nv_bfloat16 (*fl)[40] = (__nv_bfloat16(*)[40])(dyn + 20480);
    __nv_bfloat16* esm = (__nv_bfloat16*)dyn;   // aliases tiles (used after)

    const int b  = blockIdx.z;
    const int m0 = blockIdx.x * 128;
    const int n0 = blockIdx.y * 64;
    const int tid = threadIdx.x;

    for (int idx = tid; idx < CQ * 64; idx += 256) {
        int c = idx >> 6, i = idx & 63;
        float gv = GBUF[((size_t)b * CQ + c) * NN + n0 + i];
        __nv_bfloat16 h1 = __float2bfloat16(gv);
        gh[i][c] = h1;
        gl[i][c] = __float2bfloat16(gv - __bfloat162float(h1));
    }
    for (int idx = tid; idx < CQ * 128; idx += 256) {
        int c = idx >> 7, i = idx & 127;
        float fv = FBUF[((size_t)b * CQ + c) * NN + m0 + i];
        __nv_bfloat16 h2 = __float2bfloat16(fv);
        fh[i][c] = h2;
        fl[i][c] = __float2bfloat16(fv - __bfloat162float(h2));
    }
    __syncthreads();

    const int w = tid >> 5, lane = tid & 31;
    const int nw = w >> 2, mw = w & 3;
    const int a_roff = ((lane >> 3) & 1) * 8 + (lane & 7);
    const int a_koff = lane >> 4;
    const int bl = lane & 15;
    const int b_roff = bl & 7, b_koff = bl >> 3;

    const uint32_t gh_b = smem_u32(gh), gl_b = smem_u32(gl);
    const uint32_t fh_b = smem_u32(fh), fl_b = smem_u32(fl);

    float acc[2][4][4] = {};
    #pragma unroll
    for (int ks = 0; ks < 2; ks++) {
        uint32_t Ah[2][4], Al[2][4];
        #pragma unroll
        for (int at = 0; at < 2; at++) {
            int row = nw * 32 + at * 16 + a_roff;
            uint32_t off = row * 80 + ks * 32 + a_koff * 16;
            ldsm4(Ah[at], gh_b + off);
            ldsm4(Al[at], gl_b + off);
        }
        #pragma unroll
        for (int bt = 0; bt < 4; bt++) {
            int row = mw * 32 + bt * 8 + b_roff;
            uint32_t off = row * 80 + ks * 32 + b_koff * 16;
            uint32_t Bh[2], Bl[2];
            ldsm2(Bh, fh_b + off);
            ldsm2(Bl, fl_b + off);
            #pragma unroll
            for (int at = 0; at < 2; at++) {
                mma16816(acc[at][bt], Ah[at], Bh);
                mma16816(acc[at][bt], Ah[at], Bl);
                mma16816(acc[at][bt], Al[at], Bh);
            }
        }
    }
    __syncthreads();   // all ldsm done before esm overwrites tiles

    // exp + store to esm[m][n] (local transpose), accumulate row-sum partials
    const float fmaxn = sqrtf(__int_as_float(FMXI[b]));
    const int g = lane >> 2, q = (lane & 3) * 2;
    #pragma unroll
    for (int at = 0; at < 2; at++) {
        int nl_lo = nw * 32 + at * 16 + g;
        int nl_hi = nl_lo + 8;
        float Mlo = GNRM[(size_t)b * NN + n0 + nl_lo] * fmaxn;
        float Mhi = GNRM[(size_t)b * NN + n0 + nl_hi] * fmaxn;
        float s_lo = 0.f, s_hi = 0.f;
        #pragma unroll
        for (int bt = 0; bt < 4; bt++) {
            int ml = mw * 32 + bt * 8 + q;
            float e0 = __expf(acc[at][bt][0] - Mlo);
            float e1 = __expf(acc[at][bt][1] - Mlo);
            float e2 = __expf(acc[at][bt][2] - Mhi);
            float e3 = __expf(acc[at][bt][3] - Mhi);
            esm[(ml    ) * PE + nl_lo] = __float2bfloat16(e0);
            esm[(ml + 1) * PE + nl_lo] = __float2bfloat16(e1);
            esm[(ml    ) * PE + nl_hi] = __float2bfloat16(e2);
            esm[(ml + 1) * PE + nl_hi] = __float2bfloat16(e3);
            s_lo += e0 + e1;
            s_hi += e2 + e3;
        }
        s_lo += __shfl_xor_sync(0xffffffffu, s_lo, 1);
        s_lo += __shfl_xor_sync(0xffffffffu, s_lo, 2);
        s_hi += __shfl_xor_sync(0xffffffffu, s_hi, 1);
        s_hi += __shfl_xor_sync(0xffffffffu, s_hi, 2);
        if ((lane & 3) == 0) {
            int col = blockIdx.x * 4 + mw;
            PSUM[((size_t)b * NN + n0 + nl_lo) * 128 + col] = s_lo;
            PSUM[((size_t)b * NN + n0 + nl_hi) * 128 + col] = s_hi;
        }
    }
    __syncthreads();

    // write out coalesced: each warp 16 m-rows; 8 lanes x 16B per row
    #pragma unroll
    for (int it = 0; it < 4; it++) {
        int ml = w * 16 + it * 4 + (lane >> 3);
        int nch = lane & 7;
        uint4 v = *(const uint4*)&esm[ml * PE + nch * 8];
        size_t dst = ((size_t)b * NN + m0 + ml) * NN + n0 + nch * 8;
        *(uint4*)&PTH[dst] = v;
    }
}

// ---------------------------------------------------------------------------
// K2b: ROWI = 1 / sum of 128 partials
// ---------------------------------------------------------------------------
__global__ __launch_bounds__(256) void reduce_sum_kernel()
{
    int r = blockIdx.x * 8 + (threadIdx.x >> 5);
    int lane = threadIdx.x & 31;
    const float* ps = PSUM + (size_t)r * 128;
    float z = (ps[lane] + ps[lane + 32]) + (ps[lane + 64] + ps[lane + 96]);
    #pragma unroll
    for (int off = 16; off; off >>= 1)
        z += __shfl_xor_sync(0xffffffffu, z, off);
    if (lane == 0) ROWI[r] = 1.f / z;
}

// ---------------------------------------------------------------------------
// K3: h'[b,c,n] = HF[b,c,n] * ROWI[b,n] -> bf16
// ---------------------------------------------------------------------------
__global__ __launch_bounds__(256) void scale_h_kernel()
{
    const int b = blockIdx.x / CPAD;
    const int c = blockIdx.x % CPAD;
    const float* hrow = HF + ((size_t)b * CPAD + c) * NN;
    const float* zrow = ROWI + (size_t)b * NN;
    __nv_bfloat16* dh = HHB + ((size_t)b * CPAD + c) * NN;

    for (int i = threadIdx.x; i < NN / 4; i += 256) {
        float4 h = *(const float4*)&hrow[i * 4];
        float4 z = *(const float4*)&zrow[i * 4];
        __nv_bfloat16 hi[4];
        hi[0] = __float2bfloat16(h.x * z.x);
        hi[1] = __float2bfloat16(h.y * z.y);
        hi[2] = __float2bfloat16(h.z * z.z);
        hi[3] = __float2bfloat16(h.w * z.w);
        *(uint2*)&dh[i * 4] = *(uint2*)hi;
    }
}

// ---------------------------------------------------------------------------
// K4: mma.sync GEMM (single pass).  D[c(144), m(128)] = H'[c,:] e[:,m]
// out = gamma * D + x.  Grid (32, 8), 256 threads (8 warps: 2 c x 4 m).
// ---------------------------------------------------------------------------
#define KB 64
#define ST_AH 0
#define ST_BH 18432
#define ST_BYTES 34816
#define SMEM_DYN (2 * ST_BYTES + 128)

__global__ __launch_bounds__(256, 1) void gemm_o_mma_kernel(
    const float* __restrict__ x, const float* __restrict__ gamma,
    float* __restrict__ out)
{
    extern __shared__ char smem_raw[];
    const uint32_t sb = (smem_u32(smem_raw) + 127) & ~127u;

    const int tid  = threadIdx.x;
    const int w    = tid >> 5;
    const int lane = tid & 31;
    const int cw   = w >> 2;           // 0 or 1
    const int mw   = w & 3;            // 0..3
    const int nct  = (cw == 0) ? 5 : 4; // c-tiles per warp (5/4 split of 9)
    const int b    = blockIdx.y;
    const int m0   = blockIdx.x * 128;

    const size_t abase = (size_t)b * CPAD;       // H' rows (c)
    const size_t bbase = (size_t)b * NN + m0;    // e^T rows (m)

    auto load_stage = [&](int st, int nk) {
        uint32_t base = sb + st * ST_BYTES;
        // A: H' hi, 144 rows x 8 16B-chunks = 1152
        for (int t = tid; t < 1152; t += 256) {
            int row = t >> 3, q = t & 7;
            const __nv_bfloat16* src = HHB + ((abase + row) << 12) + nk + q * 8;
            cpa16(base + ST_AH + row * 128 + ((q ^ (row & 7)) << 4), src);
        }
        // B: e^T, 128 rows x 8 chunks = 1024
        for (int t = tid; t < 1024; t += 256) {
            int row = t >> 3, q = t & 7;
            const __nv_bfloat16* src = PTH + ((bbase + row) << 12) + nk + q * 8;
            cpa16(base + ST_BH + row * 128 + ((q ^ (row & 7)) << 4), src);
        }
    };

    float acc[5][4][4] = {};

    load_stage(0, 0);
    CP_COMMIT();

    const int a_roff = ((lane >> 3) & 1) * 8 + (lane & 7);
    const int a_koff = lane >> 4;
    const int bl     = lane & 15;
    const int b_roff = bl & 7;
    const int b_koff = bl >> 3;

    for (int chunk = 0; chunk < NN / KB; chunk++) {
        int cur = chunk & 1;
        if (chunk + 1 < NN / KB) {
            load_stage(cur ^ 1, (chunk + 1) * KB);
            CP_COMMIT();
            CP_WAIT1();
        } else {
            CP_WAIT0();
        }
        __syncthreads();

        uint32_t base = sb + cur * ST_BYTES;
        #pragma unroll
        for (int ks = 0; ks < 4; ks++) {
            uint32_t Ah[5][4], Bh[4][2];
            #pragma unroll
            for (int ct = 0; ct < 5; ct++) {
                if (ct < nct) {
                    int row = cw * 80 + ct * 16 + a_roff;
                    int kch = ks * 2 + a_koff;
                    ldsm4(Ah[ct], base + ST_AH + row * 128 + ((kch ^ (row & 7)) << 4));
                }
            }
            #pragma unroll
            for (int mt = 0; mt < 4; mt++) {
                int row = mw * 32 + mt * 8 + b_roff;
                int kch = ks * 2 + b_koff;
                ldsm2(Bh[mt], base + ST_BH + row * 128 + ((kch ^ (row & 7)) << 4));
            }
            #pragma unroll
            for (int ct = 0; ct < 5; ct++) {
                if (ct < nct) {
                    #pragma unroll
                    for (int mt = 0; mt < 4; mt++)
                        mma16816(acc[ct][mt], Ah[ct], Bh[mt]);
                }
            }
        }
        __syncthreads();
    }

    // ---- epilogue: out = gamma*D + x ----
    const float gm = __ldg(gamma);
    const int g = lane >> 2;
    const int mo = (lane & 3) * 2;
    #pragma unroll
    for (int ct = 0; ct < 5; ct++) {
        if (ct >= nct) break;
        int c0 = cw * 80 + ct * 16 + g;
        #pragma unroll
        for (int mt = 0; mt < 4; mt++) {
            int m = m0 + mw * 32 + mt * 8 + mo;
            if (c0 < CC) {
                size_t idx = ((size_t)b * CC + c0) * NN + m;
                float2 xv = *(const float2*)&x[idx];
                *(float2*)&out[idx] = make_float2(gm * acc[ct][mt][0] + xv.x,
                                                  gm * acc[ct][mt][1] + xv.y);
            }
            if (c0 + 8 < CC) {
                size_t idx = ((size_t)b * CC + c0 + 8) * NN + m;
                float2 xv = *(const float2*)&x[idx];
                *(float2*)&out[idx] = make_float2(gm * acc[ct][mt][2] + xv.x,
                                                  gm * acc[ct][mt][3] + xv.y);
            }
        }
    }
}

// ---------------------------------------------------------------------------
extern "C" void kernel_launch(void* const* d_in, const int* in_sizes, int n_in,
                              void* d_out, int out_size)
{
    const float* x   = (const float*)d_in[0];
    const float* wF  = (const float*)d_in[1];
    const float* bF  = (const float*)d_in[2];
    const float* fw  = (const float*)d_in[3];
    const float* fbe = (const float*)d_in[4];
    const float* fm  = (const float*)d_in[5];
    const float* fv  = (const float*)d_in[6];
    const float* wG  = (const float*)d_in[7];
    const float* bG  = (const float*)d_in[8];
    const float* gw  = (const float*)d_in[9];
    const float* gbe = (const float*)d_in[10];
    const float* gm  = (const float*)d_in[11];
    const float* gv  = (const float*)d_in[12];
    const float* wH  = (const float*)d_in[13];
    const float* bH  = (const float*)d_in[14];
    const float* hw  = (const float*)d_in[15];
    const float* hbe = (const float*)d_in[16];
    const float* hm  = (const float*)d_in[17];
    const float* hv  = (const float*)d_in[18];
    const float* gamma = (const float*)d_in[19];
    float* out = (float*)d_out;

    cudaFuncSetAttribute(gemm_se_kernel,
                         cudaFuncAttributeMaxDynamicSharedMemorySize, SE_SMEM);
    cudaFuncSetAttribute(gemm_o_mma_kernel,
                         cudaFuncAttributeMaxDynamicSharedMemorySize, SMEM_DYN);

    proj_kernel<<<dim3(NN / 64, BB), 256>>>(x,
        wF, bF, fw, fbe, fm, fv,
        wG, bG, gw, gbe, gm, gv,
        wH, bH, hw, hbe, hm, hv);
    norms_kernel<<<dim3(NN / 256, BB), 256>>>();
    gemm_se_kernel<<<dim3(NN / 128, NN / 64, BB), 256, SE_SMEM>>>();
    reduce_sum_kernel<<<BB * NN / 8, 256>>>();
    scale_h_kernel<<<BB * CPAD, 256>>>();
    gemm_o_mma_kernel<<<dim3(NN / 128, BB), 256, SMEM_DYN>>>(x, gamma, out);
}

// round 7
// speedup vs baseline: 3.6700x; 1.3682x over previous
#include <cuda_runtime.h>
#include <cuda_bf16.h>
#include <cstdint>

#define BB 8
#define CC 130
#define CPAD 144          // c padded to 9 x 16 for MMA M tiles
#define CQ 32
#define NN 4096
#define BN_EPS 1e-5f

// ---------------- static device scratch ----------------
__device__ float FBUF[BB * CQ * NN];
__device__ float GBUF[BB * CQ * NN];
__device__ float HF[(size_t)BB * CPAD * NN];            // h fp32 (pre-scale)
__device__ __nv_bfloat16 HHB[(size_t)BB * CPAD * NN];   // h' = h*invZ (bf16)
__device__ __nv_bfloat16 PTH[(size_t)BB * NN * NN];     // e^T: [b][m][n] bf16
__device__ __nv_bfloat16 GTH[(size_t)BB * NN * CQ];     // g^T hi [b][n][32]
__device__ __nv_bfloat16 GTL[(size_t)BB * NN * CQ];     // g^T lo
__device__ __nv_bfloat16 FTH[(size_t)BB * NN * CQ];     // f^T hi
__device__ __nv_bfloat16 FTL[(size_t)BB * NN * CQ];     // f^T lo
__device__ float PSUM[(size_t)BB * NN * 64];
__device__ float GNRM[BB * NN];                          // ||g_n||
__device__ int   FMXI[BB];                               // max_m ||f_m||^2 (bits)
__device__ float ROWI[BB * NN];                          // 1/Z

// ---------------- helpers ----------------
__device__ __forceinline__ uint32_t smem_u32(const void* p) {
    uint32_t a;
    asm("{ .reg .u64 t; cvta.to.shared.u64 t, %1; cvt.u32.u64 %0, t; }" : "=r"(a) : "l"(p));
    return a;
}
__device__ __forceinline__ void cpa16(uint32_t dst, const void* src) {
    asm volatile("cp.async.cg.shared.global [%0], [%1], 16;" :: "r"(dst), "l"(src));
}
#define CP_COMMIT() asm volatile("cp.async.commit_group;" ::: "memory")
#define CP_WAIT2()  asm volatile("cp.async.wait_group 2;" ::: "memory")
#define CP_WAIT1()  asm volatile("cp.async.wait_group 1;" ::: "memory")
#define CP_WAIT0()  asm volatile("cp.async.wait_group 0;" ::: "memory")

__device__ __forceinline__ void ldsm4(uint32_t* r, uint32_t addr) {
    asm volatile("ldmatrix.sync.aligned.m8n8.x4.shared.b16 {%0,%1,%2,%3}, [%4];"
                 : "=r"(r[0]), "=r"(r[1]), "=r"(r[2]), "=r"(r[3]) : "r"(addr));
}
__device__ __forceinline__ void ldsm2(uint32_t* r, uint32_t addr) {
    asm volatile("ldmatrix.sync.aligned.m8n8.x2.shared.b16 {%0,%1}, [%2];"
                 : "=r"(r[0]), "=r"(r[1]) : "r"(addr));
}
__device__ __forceinline__ void mma16816(float* d, const uint32_t* a, const uint32_t* b) {
    asm volatile("mma.sync.aligned.m16n8k16.row.col.f32.bf16.bf16.f32 "
                 "{%0,%1,%2,%3}, {%4,%5,%6,%7}, {%8,%9}, {%0,%1,%2,%3};"
                 : "+f"(d[0]), "+f"(d[1]), "+f"(d[2]), "+f"(d[3])
                 : "r"(a[0]), "r"(a[1]), "r"(a[2]), "r"(a[3]), "r"(b[0]), "r"(b[1]));
}

// ---------------------------------------------------------------------------
// K1: fused 1x1-conv + BN + ReLU. F,G -> fp32; H -> fp32 HF (+ zero pad rows)
// ---------------------------------------------------------------------------
__global__ __launch_bounds__(256) void proj_kernel(
    const float* __restrict__ x,
    const float* __restrict__ wF, const float* __restrict__ bF,
    const float* __restrict__ fw, const float* __restrict__ fbe,
    const float* __restrict__ fm, const float* __restrict__ fv,
    const float* __restrict__ wG, const float* __restrict__ bG,
    const float* __restrict__ gw, const float* __restrict__ gbe,
    const float* __restrict__ gm, const float* __restrict__ gv,
    const float* __restrict__ wH, const float* __restrict__ bH,
    const float* __restrict__ hw, const float* __restrict__ hbe,
    const float* __restrict__ hm, const float* __restrict__ hv)
{
    __shared__ float xs[CC][64];
    const int b  = blockIdx.y;
    const int n0 = blockIdx.x * 64;
    const int tid = threadIdx.x;

    for (int idx = tid; idx < CC * 64; idx += 256) {
        int c = idx >> 6, i = idx & 63;
        xs[c][i] = x[((size_t)b * CC + c) * NN + n0 + i];
    }
    __syncthreads();

    const int tx = tid & 15;
    const int ty = tid >> 4;

    for (int o = ty; o < 2 * CQ + CPAD; o += 16) {
        if (o >= 2 * CQ + CC) {
            int oo = o - 2 * CQ;    // pad rows [130,144): zero
            *(float4*)&HF[((size_t)b * CPAD + oo) * NN + n0 + tx * 4] =
                make_float4(0.f, 0.f, 0.f, 0.f);
            continue;
        }
        const float* wrow;
        const float *pb, *pw, *pbe, *pm, *pv;
        int oo, which;
        if (o < CQ)          { oo = o;          which = 0; wrow = wF + oo * CC; pb = bF; pw = fw; pbe = fbe; pm = fm; pv = fv; }
        else if (o < 2 * CQ) { oo = o - CQ;     which = 1; wrow = wG + oo * CC; pb = bG; pw = gw; pbe = gbe; pm = gm; pv = gv; }
        else                 { oo = o - 2 * CQ; which = 2; wrow = wH + oo * CC; pb = bH; pw = hw; pbe = hbe; pm = hm; pv = hv; }

        float a0 = 0.f, a1 = 0.f, a2 = 0.f, a3 = 0.f;
        #pragma unroll 2
        for (int c = 0; c < CC; c++) {
            float wv = __ldg(wrow + c);
            float4 xv = *(const float4*)&xs[c][tx * 4];
            a0 += wv * xv.x; a1 += wv * xv.y; a2 += wv * xv.z; a3 += wv * xv.w;
        }
        float scale = __ldg(pw + oo) * rsqrtf(__ldg(pv + oo) + BN_EPS);
        float bias  = __ldg(pb + oo) - __ldg(pm + oo);
        float be    = __ldg(pbe + oo);
        float4 r;
        r.x = fmaxf(scale * (a0 + bias) + be, 0.f);
        r.y = fmaxf(scale * (a1 + bias) + be, 0.f);
        r.z = fmaxf(scale * (a2 + bias) + be, 0.f);
        r.w = fmaxf(scale * (a3 + bias) + be, 0.f);
        if (which == 2) {
            *(float4*)&HF[((size_t)b * CPAD + oo) * NN + n0 + tx * 4] = r;
        } else {
            float* dst = (which == 0 ? FBUF : GBUF) + ((size_t)b * CQ + oo) * NN;
            *(float4*)&dst[n0 + tx * 4] = r;
        }
    }
}

// ---------------------------------------------------------------------------
// K1b: norms + transposed bf16 hi/lo emit.
//   GNRM[b,n] = ||g_:,n||, FMXI[b] = max_n ||f_:,n||^2 (monotone atomicMax)
//   GTH/GTL/FTH/FTL[b][n][32] = bf16 hi/lo of g^T, f^T
// ---------------------------------------------------------------------------
__global__ __launch_bounds__(256) void norms_kernel()
{
    const int b = blockIdx.y;
    const int n = blockIdx.x * 256 + threadIdx.x;
    float fs = 0.f, gs = 0.f;
    __nv_bfloat16 fh[CQ], fl[CQ], gh[CQ], gl[CQ];
    #pragma unroll
    for (int c = 0; c < CQ; c++) {
        float fv = FBUF[((size_t)b * CQ + c) * NN + n];
        float gv = GBUF[((size_t)b * CQ + c) * NN + n];
        fs += fv * fv;
        gs += gv * gv;
        fh[c] = __float2bfloat16(fv);
        fl[c] = __float2bfloat16(fv - __bfloat162float(fh[c]));
        gh[c] = __float2bfloat16(gv);
        gl[c] = __float2bfloat16(gv - __bfloat162float(gh[c]));
    }
    size_t rbase = ((size_t)b * NN + n) * CQ;
    #pragma unroll
    for (int q = 0; q < 4; q++) {
        *(uint4*)&FTH[rbase + q * 8] = ((uint4*)fh)[q];
        *(uint4*)&FTL[rbase + q * 8] = ((uint4*)fl)[q];
        *(uint4*)&GTH[rbase + q * 8] = ((uint4*)gh)[q];
        *(uint4*)&GTL[rbase + q * 8] = ((uint4*)gl)[q];
    }
    GNRM[(size_t)b * NN + n] = sqrtf(gs);
    #pragma unroll
    for (int off = 16; off; off >>= 1)
        fs = fmaxf(fs, __shfl_xor_sync(0xffffffffu, fs, off));
    if ((threadIdx.x & 31) == 0)
        atomicMax(&FMXI[b], __float_as_int(fs));   // fs >= 0: int-max == float-max
}

// ---------------------------------------------------------------------------
// K2: S recompute (bf16x3) + e = exp(S - M~) -> PTH (transposed via smem)
//     + per-(row, 64-m) sum partials into PSUM[.., 64].
// Block: 128n x 128m; 8 warps (4n x 2m). Tiles cp.async'd from GT*/FT*.
// Dyn smem: 4 tiles x 10240 B (128 rows x 80 B), aliased by esm[128][136].
// ---------------------------------------------------------------------------
#define PE 136
#define SE_SMEM 40960

__global__ __launch_bounds__(256) void gemm_se_kernel()
{
    extern __shared__ char dyn[];
    const uint32_t sb = smem_u32(dyn);
    __nv_bfloat16* esm = (__nv_bfloat16*)dyn;   // aliases tiles (used after)

    const int b  = blockIdx.z;
    const int m0 = blockIdx.x * 128;
    const int n0 = blockIdx.y * 128;
    const int tid = threadIdx.x;

    // async tile load: buf 0:gh 1:gl 2:fh 3:fl; 128 rows x 4 chunks each
    {
        const __nv_bfloat16* srcs[4] = {
            GTH + ((size_t)b * NN + n0) * CQ, GTL + ((size_t)b * NN + n0) * CQ,
            FTH + ((size_t)b * NN + m0) * CQ, FTL + ((size_t)b * NN + m0) * CQ };
        #pragma unroll
        for (int r = 0; r < 8; r++) {
            int t = tid + r * 256;
            int buf = t >> 9, idx = t & 511, row = idx >> 2, q = idx & 3;
            cpa16(sb + buf * 10240 + row * 80 + q * 16, srcs[buf] + row * CQ + q * 8);
        }
    }
    CP_COMMIT();
    CP_WAIT0();
    __syncthreads();

    const int w = tid >> 5, lane = tid & 31;
    const int nw = w >> 1, mw = w & 1;
    const int a_roff = ((lane >> 3) & 1) * 8 + (lane & 7);
    const int a_koff = lane >> 4;
    const int bl = lane & 15;
    const int b_roff = bl & 7, b_koff = bl >> 3;

    const uint32_t gh_b = sb, gl_b = sb + 10240, fh_b = sb + 20480, fl_b = sb + 30720;

    float acc[2][8][4] = {};
    #pragma unroll
    for (int ks = 0; ks < 2; ks++) {
        uint32_t Ah[2][4], Al[2][4], Bh[8][2], Bl[8][2];
        #pragma unroll
        for (int at = 0; at < 2; at++) {
            int row = nw * 32 + at * 16 + a_roff;
            uint32_t off = row * 80 + ks * 32 + a_koff * 16;
            ldsm4(Ah[at], gh_b + off);
            ldsm4(Al[at], gl_b + off);
        }
        #pragma unroll
        for (int bt = 0; bt < 8; bt++) {
            int row = mw * 64 + bt * 8 + b_roff;
            uint32_t off = row * 80 + ks * 32 + b_koff * 16;
            ldsm2(Bh[bt], fh_b + off);
            ldsm2(Bl[bt], fl_b + off);
        }
        #pragma unroll
        for (int at = 0; at < 2; at++)
            #pragma unroll
            for (int bt = 0; bt < 8; bt++) {
                mma16816(acc[at][bt], Ah[at], Bh[bt]);
                mma16816(acc[at][bt], Ah[at], Bl[bt]);
                mma16816(acc[at][bt], Al[at], Bh[bt]);
            }
    }
    __syncthreads();   // all ldsm done before esm overwrites tiles

    // exp + store to esm[m][n] (local transpose), accumulate row-sum partials
    const float fmaxn = sqrtf(__int_as_float(FMXI[b]));
    const int g = lane >> 2, q = (lane & 3) * 2;
    #pragma unroll
    for (int at = 0; at < 2; at++) {
        int nl_lo = nw * 32 + at * 16 + g;
        int nl_hi = nl_lo + 8;
        float Mlo = GNRM[(size_t)b * NN + n0 + nl_lo] * fmaxn;
        float Mhi = GNRM[(size_t)b * NN + n0 + nl_hi] * fmaxn;
        float s_lo = 0.f, s_hi = 0.f;
        #pragma unroll
        for (int bt = 0; bt < 8; bt++) {
            int ml = mw * 64 + bt * 8 + q;
            float e0 = __expf(acc[at][bt][0] - Mlo);
            float e1 = __expf(acc[at][bt][1] - Mlo);
            float e2 = __expf(acc[at][bt][2] - Mhi);
            float e3 = __expf(acc[at][bt][3] - Mhi);
            esm[(ml    ) * PE + nl_lo] = __float2bfloat16(e0);
            esm[(ml + 1) * PE + nl_lo] = __float2bfloat16(e1);
            esm[(ml    ) * PE + nl_hi] = __float2bfloat16(e2);
            esm[(ml + 1) * PE + nl_hi] = __float2bfloat16(e3);
            s_lo += e0 + e1;
            s_hi += e2 + e3;
        }
        s_lo += __shfl_xor_sync(0xffffffffu, s_lo, 1);
        s_lo += __shfl_xor_sync(0xffffffffu, s_lo, 2);
        s_hi += __shfl_xor_sync(0xffffffffu, s_hi, 1);
        s_hi += __shfl_xor_sync(0xffffffffu, s_hi, 2);
        if ((lane & 3) == 0) {
            int col = blockIdx.x * 2 + mw;
            PSUM[((size_t)b * NN + n0 + nl_lo) * 64 + col] = s_lo;
            PSUM[((size_t)b * NN + n0 + nl_hi) * 64 + col] = s_hi;
        }
    }
    __syncthreads();

    // write out coalesced: warp handles 2 m-rows per iter, 16 lanes per row
    const int nch = lane & 15;
    #pragma unroll
    for (int it = 0; it < 8; it++) {
        int ml = it * 16 + w * 2 + (lane >> 4);
        uint4 v = *(const uint4*)&esm[ml * PE + nch * 8];
        size_t dst = ((size_t)b * NN + m0 + ml) * NN + n0 + nch * 8;
        *(uint4*)&PTH[dst] = v;
    }
}

// ---------------------------------------------------------------------------
// K2b: ROWI = 1 / sum of 64 partials
// ---------------------------------------------------------------------------
__global__ __launch_bounds__(256) void reduce_sum_kernel()
{
    int r = blockIdx.x * 8 + (threadIdx.x >> 5);
    int lane = threadIdx.x & 31;
    const float* ps = PSUM + (size_t)r * 64;
    float z = ps[lane] + ps[lane + 32];
    #pragma unroll
    for (int off = 16; off; off >>= 1)
        z += __shfl_xor_sync(0xffffffffu, z, off);
    if (lane == 0) ROWI[r] = 1.f / z;
}

// ---------------------------------------------------------------------------
// K3: h'[b,c,n] = HF[b,c,n] * ROWI[b,n] -> bf16
// ---------------------------------------------------------------------------
__global__ __launch_bounds__(256) void scale_h_kernel()
{
    const int b = blockIdx.x / CPAD;
    const int c = blockIdx.x % CPAD;
    const float* hrow = HF + ((size_t)b * CPAD + c) * NN;
    const float* zrow = ROWI + (size_t)b * NN;
    __nv_bfloat16* dh = HHB + ((size_t)b * CPAD + c) * NN;

    for (int i = threadIdx.x; i < NN / 4; i += 256) {
        float4 h = *(const float4*)&hrow[i * 4];
        float4 z = *(const float4*)&zrow[i * 4];
        __nv_bfloat16 hi[4];
        hi[0] = __float2bfloat16(h.x * z.x);
        hi[1] = __float2bfloat16(h.y * z.y);
        hi[2] = __float2bfloat16(h.z * z.z);
        hi[3] = __float2bfloat16(h.w * z.w);
        *(uint2*)&dh[i * 4] = *(uint2*)hi;
    }
}

// ---------------------------------------------------------------------------
// K4: mma.sync GEMM (single pass, 3-stage pipeline).
// D[c(144), m(128)] = H'[c,:] e[:,m];  out = gamma * D + x.
// Grid (32, 8), 256 threads (8 warps: 2 c x 4 m).
// ---------------------------------------------------------------------------
#define KB 64
#define ST_AH 0
#define ST_BH 18432
#define ST_BYTES 34816
#define SMEM_DYN (3 * ST_BYTES + 128)

__global__ __launch_bounds__(256, 1) void gemm_o_mma_kernel(
    const float* __restrict__ x, const float* __restrict__ gamma,
    float* __restrict__ out)
{
    extern __shared__ char smem_raw[];
    const uint32_t sb = (smem_u32(smem_raw) + 127) & ~127u;

    const int tid  = threadIdx.x;
    const int w    = tid >> 5;
    const int lane = tid & 31;
    const int cw   = w >> 2;           // 0 or 1
    const int mw   = w & 3;            // 0..3
    const int nct  = (cw == 0) ? 5 : 4; // c-tiles per warp (5/4 split of 9)
    const int b    = blockIdx.y;
    const int m0   = blockIdx.x * 128;

    const size_t abase = (size_t)b * CPAD;       // H' rows (c)
    const size_t bbase = (size_t)b * NN + m0;    // e^T rows (m)

    auto load_stage = [&](int st, int nk) {
        uint32_t base = sb + st * ST_BYTES;
        // A: H' hi, 144 rows x 8 16B-chunks = 1152
        for (int t = tid; t < 1152; t += 256) {
            int row = t >> 3, q = t & 7;
            const __nv_bfloat16* src = HHB + ((abase + row) << 12) + nk + q * 8;
            cpa16(base + ST_AH + row * 128 + ((q ^ (row & 7)) << 4), src);
        }
        // B: e^T, 128 rows x 8 chunks = 1024
        for (int t = tid; t < 1024; t += 256) {
            int row = t >> 3, q = t & 7;
            const __nv_bfloat16* src = PTH + ((bbase + row) << 12) + nk + q * 8;
            cpa16(base + ST_BH + row * 128 + ((q ^ (row & 7)) << 4), src);
        }
    };

    float acc[5][4][4] = {};

    load_stage(0, 0);
    CP_COMMIT();
    load_stage(1, KB);
    CP_COMMIT();

    const int a_roff = ((lane >> 3) & 1) * 8 + (lane & 7);
    const int a_koff = lane >> 4;
    const int bl     = lane & 15;
    const int b_roff = bl & 7;
    const int b_koff = bl >> 3;

    for (int chunk = 0; chunk < NN / KB; chunk++) {
        int cur = chunk % 3;
        if (chunk + 2 < NN / KB) {
            load_stage((chunk + 2) % 3, (chunk + 2) * KB);
            CP_COMMIT();
            CP_WAIT2();
        } else if (chunk + 1 < NN / KB) {
            CP_WAIT1();
        } else {
            CP_WAIT0();
        }
        __syncthreads();

        uint32_t base = sb + cur * ST_BYTES;
        #pragma unroll
        for (int ks = 0; ks < 4; ks++) {
            uint32_t Ah[5][4], Bh[4][2];
            #pragma unroll
            for (int ct = 0; ct < 5; ct++) {
                if (ct < nct) {
                    int row = cw * 80 + ct * 16 + a_roff;
                    int kch = ks * 2 + a_koff;
                    ldsm4(Ah[ct], base + ST_AH + row * 128 + ((kch ^ (row & 7)) << 4));
                }
            }
            #pragma unroll
            for (int mt = 0; mt < 4; mt++) {
                int row = mw * 32 + mt * 8 + b_roff;
                int kch = ks * 2 + b_koff;
                ldsm2(Bh[mt], base + ST_BH + row * 128 + ((kch ^ (row & 7)) << 4));
            }
            #pragma unroll
            for (int ct = 0; ct < 5; ct++) {
                if (ct < nct) {
                    #pragma unroll
                    for (int mt = 0; mt < 4; mt++)
                        mma16816(acc[ct][mt], Ah[ct], Bh[mt]);
                }
            }
        }
        __syncthreads();
    }

    // ---- epilogue: out = gamma*D + x ----
    const float gm = __ldg(gamma);
    const int g = lane >> 2;
    const int mo = (lane & 3) * 2;
    #pragma unroll
    for (int ct = 0; ct < 5; ct++) {
        if (ct >= nct) break;
        int c0 = cw * 80 + ct * 16 + g;
        #pragma unroll
        for (int mt = 0; mt < 4; mt++) {
            int m = m0 + mw * 32 + mt * 8 + mo;
            if (c0 < CC) {
                size_t idx = ((size_t)b * CC + c0) * NN + m;
                float2 xv = *(const float2*)&x[idx];
                *(float2*)&out[idx] = make_float2(gm * acc[ct][mt][0] + xv.x,
                                                  gm * acc[ct][mt][1] + xv.y);
            }
            if (c0 + 8 < CC) {
                size_t idx = ((size_t)b * CC + c0 + 8) * NN + m;
                float2 xv = *(const float2*)&x[idx];
                *(float2*)&out[idx] = make_float2(gm * acc[ct][mt][2] + xv.x,
                                                  gm * acc[ct][mt][3] + xv.y);
            }
        }
    }
}

// ---------------------------------------------------------------------------
extern "C" void kernel_launch(void* const* d_in, const int* in_sizes, int n_in,
                              void* d_out, int out_size)
{
    const float* x   = (const float*)d_in[0];
    const float* wF  = (const float*)d_in[1];
    const float* bF  = (const float*)d_in[2];
    const float* fw  = (const float*)d_in[3];
    const float* fbe = (const float*)d_in[4];
    const float* fm  = (const float*)d_in[5];
    const float* fv  = (const float*)d_in[6];
    const float* wG  = (const float*)d_in[7];
    const float* bG  = (const float*)d_in[8];
    const float* gw  = (const float*)d_in[9];
    const float* gbe = (const float*)d_in[10];
    const float* gm  = (const float*)d_in[11];
    const float* gv  = (const float*)d_in[12];
    const float* wH  = (const float*)d_in[13];
    const float* bH  = (const float*)d_in[14];
    const float* hw  = (const float*)d_in[15];
    const float* hbe = (const float*)d_in[16];
    const float* hm  = (const float*)d_in[17];
    const float* hv  = (const float*)d_in[18];
    const float* gamma = (const float*)d_in[19];
    float* out = (float*)d_out;

    cudaFuncSetAttribute(gemm_se_kernel,
                         cudaFuncAttributeMaxDynamicSharedMemorySize, SE_SMEM);
    cudaFuncSetAttribute(gemm_o_mma_kernel,
                         cudaFuncAttributeMaxDynamicSharedMemorySize, SMEM_DYN);

    proj_kernel<<<dim3(NN / 64, BB), 256>>>(x,
        wF, bF, fw, fbe, fm, fv,
        wG, bG, gw, gbe, gm, gv,
        wH, bH, hw, hbe, hm, hv);
    norms_kernel<<<dim3(NN / 256, BB), 256>>>();
    gemm_se_kernel<<<dim3(NN / 128, NN / 128, BB), 256, SE_SMEM>>>();
    reduce_sum_kernel<<<BB * NN / 8, 256>>>();
    scale_h_kernel<<<BB * CPAD, 256>>>();
    gemm_o_mma_kernel<<<dim3(NN / 128, BB), 256, SMEM_DYN>>>(x, gamma, out);
}

// round 8
// speedup vs baseline: 3.7997x; 1.0353x over previous
#include <cuda_runtime.h>
#include <cuda_bf16.h>
#include <cstdint>

#define BB 8
#define CC 130
#define CPAD 144          // c padded to 9 x 16 for MMA M tiles
#define CQ 32
#define NN 4096
#define BN_EPS 1e-5f

// ---------------- static device scratch ----------------
__device__ float FBUF[BB * CQ * NN];
__device__ float GBUF[BB * CQ * NN];
__device__ float HF[(size_t)BB * CPAD * NN];            // h fp32 (pre-scale)
__device__ __nv_bfloat16 HHB[(size_t)BB * CPAD * NN];   // h' = h*invZ (bf16)
__device__ __nv_bfloat16 PTH[(size_t)BB * NN * NN];     // e^T: [b][m][n] bf16
__device__ __nv_bfloat16 GTH[(size_t)BB * NN * CQ];     // g^T hi [b][n][32]
__device__ __nv_bfloat16 GTL[(size_t)BB * NN * CQ];     // g^T lo
__device__ __nv_bfloat16 FTH[(size_t)BB * NN * CQ];     // f^T hi
__device__ __nv_bfloat16 FTL[(size_t)BB * NN * CQ];     // f^T lo
__device__ float PSUM[(size_t)BB * NN * 64];
__device__ float GNRM[BB * NN];                          // ||g_n||
__device__ int   FMXI[BB];                               // max_m ||f_m||^2 (bits)
__device__ float ROWI[BB * NN];                          // 1/Z

// ---------------- helpers ----------------
__device__ __forceinline__ uint32_t smem_u32(const void* p) {
    uint32_t a;
    asm("{ .reg .u64 t; cvta.to.shared.u64 t, %1; cvt.u32.u64 %0, t; }" : "=r"(a) : "l"(p));
    return a;
}
__device__ __forceinline__ void cpa16(uint32_t dst, const void* src) {
    asm volatile("cp.async.cg.shared.global [%0], [%1], 16;" :: "r"(dst), "l"(src));
}
#define CP_COMMIT() asm volatile("cp.async.commit_group;" ::: "memory")
#define CP_WAIT1()  asm volatile("cp.async.wait_group 1;" ::: "memory")
#define CP_WAIT0()  asm volatile("cp.async.wait_group 0;" ::: "memory")

__device__ __forceinline__ void ldsm4(uint32_t* r, uint32_t addr) {
    asm volatile("ldmatrix.sync.aligned.m8n8.x4.shared.b16 {%0,%1,%2,%3}, [%4];"
                 : "=r"(r[0]), "=r"(r[1]), "=r"(r[2]), "=r"(r[3]) : "r"(addr));
}
__device__ __forceinline__ void ldsm2(uint32_t* r, uint32_t addr) {
    asm volatile("ldmatrix.sync.aligned.m8n8.x2.shared.b16 {%0,%1}, [%2];"
                 : "=r"(r[0]), "=r"(r[1]) : "r"(addr));
}
__device__ __forceinline__ void mma16816(float* d, const uint32_t* a, const uint32_t* b) {
    asm volatile("mma.sync.aligned.m16n8k16.row.col.f32.bf16.bf16.f32 "
                 "{%0,%1,%2,%3}, {%4,%5,%6,%7}, {%8,%9}, {%0,%1,%2,%3};"
                 : "+f"(d[0]), "+f"(d[1]), "+f"(d[2]), "+f"(d[3])
                 : "r"(a[0]), "r"(a[1]), "r"(a[2]), "r"(a[3]), "r"(b[0]), "r"(b[1]));
}

// ---------------------------------------------------------------------------
// K1: fused 1x1-conv + BN + ReLU. F,G -> fp32; H -> fp32 HF (+ zero pad rows)
// ---------------------------------------------------------------------------
__global__ __launch_bounds__(256) void proj_kernel(
    const float* __restrict__ x,
    const float* __restrict__ wF, const float* __restrict__ bF,
    const float* __restrict__ fw, const float* __restrict__ fbe,
    const float* __restrict__ fm, const float* __restrict__ fv,
    const float* __restrict__ wG, const float* __restrict__ bG,
    const float* __restrict__ gw, const float* __restrict__ gbe,
    const float* __restrict__ gm, const float* __restrict__ gv,
    const float* __restrict__ wH, const float* __restrict__ bH,
    const float* __restrict__ hw, const float* __restrict__ hbe,
    const float* __restrict__ hm, const float* __restrict__ hv)
{
    __shared__ float xs[CC][64];
    const int b  = blockIdx.y;
    const int n0 = blockIdx.x * 64;
    const int tid = threadIdx.x;

    for (int idx = tid; idx < CC * 64; idx += 256) {
        int c = idx >> 6, i = idx & 63;
        xs[c][i] = x[((size_t)b * CC + c) * NN + n0 + i];
    }
    __syncthreads();

    const int tx = tid & 15;
    const int ty = tid >> 4;

    for (int o = ty; o < 2 * CQ + CPAD; o += 16) {
        if (o >= 2 * CQ + CC) {
            int oo = o - 2 * CQ;    // pad rows [130,144): zero
            *(float4*)&HF[((size_t)b * CPAD + oo) * NN + n0 + tx * 4] =
                make_float4(0.f, 0.f, 0.f, 0.f);
            continue;
        }
        const float* wrow;
        const float *pb, *pw, *pbe, *pm, *pv;
        int oo, which;
        if (o < CQ)          { oo = o;          which = 0; wrow = wF + oo * CC; pb = bF; pw = fw; pbe = fbe; pm = fm; pv = fv; }
        else if (o < 2 * CQ) { oo = o - CQ;     which = 1; wrow = wG + oo * CC; pb = bG; pw = gw; pbe = gbe; pm = gm; pv = gv; }
        else                 { oo = o - 2 * CQ; which = 2; wrow = wH + oo * CC; pb = bH; pw = hw; pbe = hbe; pm = hm; pv = hv; }

        float a0 = 0.f, a1 = 0.f, a2 = 0.f, a3 = 0.f;
        #pragma unroll 2
        for (int c = 0; c < CC; c++) {
            float wv = __ldg(wrow + c);
            float4 xv = *(const float4*)&xs[c][tx * 4];
            a0 += wv * xv.x; a1 += wv * xv.y; a2 += wv * xv.z; a3 += wv * xv.w;
        }
        float scale = __ldg(pw + oo) * rsqrtf(__ldg(pv + oo) + BN_EPS);
        float bias  = __ldg(pb + oo) - __ldg(pm + oo);
        float be    = __ldg(pbe + oo);
        float4 r;
        r.x = fmaxf(scale * (a0 + bias) + be, 0.f);
        r.y = fmaxf(scale * (a1 + bias) + be, 0.f);
        r.z = fmaxf(scale * (a2 + bias) + be, 0.f);
        r.w = fmaxf(scale * (a3 + bias) + be, 0.f);
        if (which == 2) {
            *(float4*)&HF[((size_t)b * CPAD + oo) * NN + n0 + tx * 4] = r;
        } else {
            float* dst = (which == 0 ? FBUF : GBUF) + ((size_t)b * CQ + oo) * NN;
            *(float4*)&dst[n0 + tx * 4] = r;
        }
    }
}

// ---------------------------------------------------------------------------
// K1b: norms + transposed bf16 hi/lo emit.
// ---------------------------------------------------------------------------
__global__ __launch_bounds__(256) void norms_kernel()
{
    const int b = blockIdx.y;
    const int n = blockIdx.x * 256 + threadIdx.x;
    float fs = 0.f, gs = 0.f;
    __nv_bfloat16 fh[CQ], fl[CQ], gh[CQ], gl[CQ];
    #pragma unroll
    for (int c = 0; c < CQ; c++) {
        float fv = FBUF[((size_t)b * CQ + c) * NN + n];
        float gv = GBUF[((size_t)b * CQ + c) * NN + n];
        fs += fv * fv;
        gs += gv * gv;
        fh[c] = __float2bfloat16(fv);
        fl[c] = __float2bfloat16(fv - __bfloat162float(fh[c]));
        gh[c] = __float2bfloat16(gv);
        gl[c] = __float2bfloat16(gv - __bfloat162float(gh[c]));
    }
    size_t rbase = ((size_t)b * NN + n) * CQ;
    #pragma unroll
    for (int q = 0; q < 4; q++) {
        *(uint4*)&FTH[rbase + q * 8] = ((uint4*)fh)[q];
        *(uint4*)&FTL[rbase + q * 8] = ((uint4*)fl)[q];
        *(uint4*)&GTH[rbase + q * 8] = ((uint4*)gh)[q];
        *(uint4*)&GTL[rbase + q * 8] = ((uint4*)gl)[q];
    }
    GNRM[(size_t)b * NN + n] = sqrtf(gs);
    #pragma unroll
    for (int off = 16; off; off >>= 1)
        fs = fmaxf(fs, __shfl_xor_sync(0xffffffffu, fs, off));
    if ((threadIdx.x & 31) == 0)
        atomicMax(&FMXI[b], __float_as_int(fs));   // fs >= 0: int-max == float-max
}

// ---------------------------------------------------------------------------
// K2: S recompute (bf16x3) + e = exp(S - M~) -> PTH (transposed via smem)
//     + per-(row, 64-m) sum partials into PSUM[.., 64].
// ---------------------------------------------------------------------------
#define PE 136
#define SE_SMEM 40960

__global__ __launch_bounds__(256) void gemm_se_kernel()
{
    extern __shared__ char dyn[];
    const uint32_t sb = smem_u32(dyn);
    __nv_bfloat16* esm = (__nv_bfloat16*)dyn;   // aliases tiles (used after)

    const int b  = blockIdx.z;
    const int m0 = blockIdx.x * 128;
    const int n0 = blockIdx.y * 128;
    const int tid = threadIdx.x;

    // async tile load: buf 0:gh 1:gl 2:fh 3:fl; 128 rows x 4 chunks each
    {
        const __nv_bfloat16* srcs[4] = {
            GTH + ((size_t)b * NN + n0) * CQ, GTL + ((size_t)b * NN + n0) * CQ,
            FTH + ((size_t)b * NN + m0) * CQ, FTL + ((size_t)b * NN + m0) * CQ };
        #pragma unroll
        for (int r = 0; r < 8; r++) {
            int t = tid + r * 256;
            int buf = t >> 9, idx = t & 511, row = idx >> 2, q = idx & 3;
            cpa16(sb + buf * 10240 + row * 80 + q * 16, srcs[buf] + row * CQ + q * 8);
        }
    }
    CP_COMMIT();
    CP_WAIT0();
    __syncthreads();

    const int w = tid >> 5, lane = tid & 31;
    const int nw = w >> 1, mw = w & 1;
    const int a_roff = ((lane >> 3) & 1) * 8 + (lane & 7);
    const int a_koff = lane >> 4;
    const int bl = lane & 15;
    const int b_roff = bl & 7, b_koff = bl >> 3;

    const uint32_t gh_b = sb, gl_b = sb + 10240, fh_b = sb + 20480, fl_b = sb + 30720;

    float acc[2][8][4] = {};
    #pragma unroll
    for (int ks = 0; ks < 2; ks++) {
        uint32_t Ah[2][4], Al[2][4], Bh[8][2], Bl[8][2];
        #pragma unroll
        for (int at = 0; at < 2; at++) {
            int row = nw * 32 + at * 16 + a_roff;
            uint32_t off = row * 80 + ks * 32 + a_koff * 16;
            ldsm4(Ah[at], gh_b + off);
            ldsm4(Al[at], gl_b + off);
        }
        #pragma unroll
        for (int bt = 0; bt < 8; bt++) {
            int row = mw * 64 + bt * 8 + b_roff;
            uint32_t off = row * 80 + ks * 32 + b_koff * 16;
            ldsm2(Bh[bt], fh_b + off);
            ldsm2(Bl[bt], fl_b + off);
        }
        #pragma unroll
        for (int at = 0; at < 2; at++)
            #pragma unroll
            for (int bt = 0; bt < 8; bt++) {
                mma16816(acc[at][bt], Ah[at], Bh[bt]);
                mma16816(acc[at][bt], Ah[at], Bl[bt]);
                mma16816(acc[at][bt], Al[at], Bh[bt]);
            }
    }
    __syncthreads();   // all ldsm done before esm overwrites tiles

    // exp + store to esm[m][n] (local transpose), accumulate row-sum partials
    const float fmaxn = sqrtf(__int_as_float(FMXI[b]));
    const int g = lane >> 2, q = (lane & 3) * 2;
    #pragma unroll
    for (int at = 0; at < 2; at++) {
        int nl_lo = nw * 32 + at * 16 + g;
        int nl_hi = nl_lo + 8;
        float Mlo = GNRM[(size_t)b * NN + n0 + nl_lo] * fmaxn;
        float Mhi = GNRM[(size_t)b * NN + n0 + nl_hi] * fmaxn;
        float s_lo = 0.f, s_hi = 0.f;
        #pragma unroll
        for (int bt = 0; bt < 8; bt++) {
            int ml = mw * 64 + bt * 8 + q;
            float e0 = __expf(acc[at][bt][0] - Mlo);
            float e1 = __expf(acc[at][bt][1] - Mlo);
            float e2 = __expf(acc[at][bt][2] - Mhi);
            float e3 = __expf(acc[at][bt][3] - Mhi);
            esm[(ml    ) * PE + nl_lo] = __float2bfloat16(e0);
            esm[(ml + 1) * PE + nl_lo] = __float2bfloat16(e1);
            esm[(ml    ) * PE + nl_hi] = __float2bfloat16(e2);
            esm[(ml + 1) * PE + nl_hi] = __float2bfloat16(e3);
            s_lo += e0 + e1;
            s_hi += e2 + e3;
        }
        s_lo += __shfl_xor_sync(0xffffffffu, s_lo, 1);
        s_lo += __shfl_xor_sync(0xffffffffu, s_lo, 2);
        s_hi += __shfl_xor_sync(0xffffffffu, s_hi, 1);
        s_hi += __shfl_xor_sync(0xffffffffu, s_hi, 2);
        if ((lane & 3) == 0) {
            int col = blockIdx.x * 2 + mw;
            PSUM[((size_t)b * NN + n0 + nl_lo) * 64 + col] = s_lo;
            PSUM[((size_t)b * NN + n0 + nl_hi) * 64 + col] = s_hi;
        }
    }
    __syncthreads();

    // write out coalesced: warp handles 2 m-rows per iter, 16 lanes per row
    const int nch = lane & 15;
    #pragma unroll
    for (int it = 0; it < 8; it++) {
        int ml = it * 16 + w * 2 + (lane >> 4);
        uint4 v = *(const uint4*)&esm[ml * PE + nch * 8];
        size_t dst = ((size_t)b * NN + m0 + ml) * NN + n0 + nch * 8;
        *(uint4*)&PTH[dst] = v;
    }
}

// ---------------------------------------------------------------------------
// K2b: ROWI = 1 / sum of 64 partials
// ---------------------------------------------------------------------------
__global__ __launch_bounds__(256) void reduce_sum_kernel()
{
    int r = blockIdx.x * 8 + (threadIdx.x >> 5);
    int lane = threadIdx.x & 31;
    const float* ps = PSUM + (size_t)r * 64;
    float z = ps[lane] + ps[lane + 32];
    #pragma unroll
    for (int off = 16; off; off >>= 1)
        z += __shfl_xor_sync(0xffffffffu, z, off);
    if (lane == 0) ROWI[r] = 1.f / z;
}

// ---------------------------------------------------------------------------
// K3: h'[b,c,n] = HF[b,c,n] * ROWI[b,n] -> bf16
// ---------------------------------------------------------------------------
__global__ __launch_bounds__(256) void scale_h_kernel()
{
    const int b = blockIdx.x / CPAD;
    const int c = blockIdx.x % CPAD;
    const float* hrow = HF + ((size_t)b * CPAD + c) * NN;
    const float* zrow = ROWI + (size_t)b * NN;
    __nv_bfloat16* dh = HHB + ((size_t)b * CPAD + c) * NN;

    for (int i = threadIdx.x; i < NN / 4; i += 256) {
        float4 h = *(const float4*)&hrow[i * 4];
        float4 z = *(const float4*)&zrow[i * 4];
        __nv_bfloat16 hi[4];
        hi[0] = __float2bfloat16(h.x * z.x);
        hi[1] = __float2bfloat16(h.y * z.y);
        hi[2] = __float2bfloat16(h.z * z.z);
        hi[3] = __float2bfloat16(h.w * z.w);
        *(uint2*)&dh[i * 4] = *(uint2*)hi;
    }
}

// ---------------------------------------------------------------------------
// K4: mma.sync GEMM (single pass, 2-stage, 2 CTAs/SM -> single wave).
// D[c(144), m(128)] = H'[c,:] e[:,m];  out = gamma * D + x.
// Grid (32, 8), 256 threads (8 warps: 2 c x 4 m).
// ---------------------------------------------------------------------------
#define KB 64
#define ST_AH 0
#define ST_BH 18432
#define ST_BYTES 34816
#define SMEM_DYN (2 * ST_BYTES + 128)

__global__ __launch_bounds__(256, 2) void gemm_o_mma_kernel(
    const float* __restrict__ x, const float* __restrict__ gamma,
    float* __restrict__ out)
{
    extern __shared__ char smem_raw[];
    const uint32_t sb = (smem_u32(smem_raw) + 127) & ~127u;

    const int tid  = threadIdx.x;
    const int w    = tid >> 5;
    const int lane = tid & 31;
    const int cw   = w >> 2;           // 0 or 1
    const int mw   = w & 3;            // 0..3
    const int nct  = (cw == 0) ? 5 : 4; // c-tiles per warp (5/4 split of 9)
    const int b    = blockIdx.y;
    const int m0   = blockIdx.x * 128;

    const size_t abase = (size_t)b * CPAD;       // H' rows (c)
    const size_t bbase = (size_t)b * NN + m0;    // e^T rows (m)

    auto load_stage = [&](int st, int nk) {
        uint32_t base = sb + st * ST_BYTES;
        // A: H' hi, 144 rows x 8 16B-chunks = 1152
        for (int t = tid; t < 1152; t += 256) {
            int row = t >> 3, q = t & 7;
            const __nv_bfloat16* src = HHB + ((abase + row) << 12) + nk + q * 8;
            cpa16(base + ST_AH + row * 128 + ((q ^ (row & 7)) << 4), src);
        }
        // B: e^T, 128 rows x 8 chunks = 1024
        for (int t = tid; t < 1024; t += 256) {
            int row = t >> 3, q = t & 7;
            const __nv_bfloat16* src = PTH + ((bbase + row) << 12) + nk + q * 8;
            cpa16(base + ST_BH + row * 128 + ((q ^ (row & 7)) << 4), src);
        }
    };

    float acc[5][4][4] = {};

    load_stage(0, 0);
    CP_COMMIT();

    const int a_roff = ((lane >> 3) & 1) * 8 + (lane & 7);
    const int a_koff = lane >> 4;
    const int bl     = lane & 15;
    const int b_roff = bl & 7;
    const int b_koff = bl >> 3;

    for (int chunk = 0; chunk < NN / KB; chunk++) {
        int cur = chunk & 1;
        if (chunk + 1 < NN / KB) {
            load_stage(cur ^ 1, (chunk + 1) * KB);
            CP_COMMIT();
            CP_WAIT1();
        } else {
            CP_WAIT0();
        }
        __syncthreads();

        uint32_t base = sb + cur * ST_BYTES;
        #pragma unroll
        for (int ks = 0; ks < 4; ks++) {
            uint32_t Bh[4][2];
            #pragma unroll
            for (int mt = 0; mt < 4; mt++) {
                int row = mw * 32 + mt * 8 + b_roff;
                int kch = ks * 2 + b_koff;
                ldsm2(Bh[mt], base + ST_BH + row * 128 + ((kch ^ (row & 7)) << 4));
            }
            #pragma unroll
            for (int ct = 0; ct < 5; ct++) {
                if (ct < nct) {
                    uint32_t Ah[4];
                    int row = cw * 80 + ct * 16 + a_roff;
                    int kch = ks * 2 + a_koff;
                    ldsm4(Ah, base + ST_AH + row * 128 + ((kch ^ (row & 7)) << 4));
                    #pragma unroll
                    for (int mt = 0; mt < 4; mt++)
                        mma16816(acc[ct][mt], Ah, Bh[mt]);
                }
            }
        }
        __syncthreads();
    }

    // ---- epilogue: out = gamma*D + x ----
    const float gm = __ldg(gamma);
    const int g = lane >> 2;
    const int mo = (lane & 3) * 2;
    #pragma unroll
    for (int ct = 0; ct < 5; ct++) {
        if (ct >= nct) break;
        int c0 = cw * 80 + ct * 16 + g;
        #pragma unroll
        for (int mt = 0; mt < 4; mt++) {
            int m = m0 + mw * 32 + mt * 8 + mo;
            if (c0 < CC) {
                size_t idx = ((size_t)b * CC + c0) * NN + m;
                float2 xv = *(const float2*)&x[idx];
                *(float2*)&out[idx] = make_float2(gm * acc[ct][mt][0] + xv.x,
                                                  gm * acc[ct][mt][1] + xv.y);
            }
            if (c0 + 8 < CC) {
                size_t idx = ((size_t)b * CC + c0 + 8) * NN + m;
                float2 xv = *(const float2*)&x[idx];
                *(float2*)&out[idx] = make_float2(gm * acc[ct][mt][2] + xv.x,
                                                  gm * acc[ct][mt][3] + xv.y);
            }
        }
    }
}

// ---------------------------------------------------------------------------
extern "C" void kernel_launch(void* const* d_in, const int* in_sizes, int n_in,
                              void* d_out, int out_size)
{
    const float* x   = (const float*)d_in[0];
    const float* wF  = (const float*)d_in[1];
    const float* bF  = (const float*)d_in[2];
    const float* fw  = (const float*)d_in[3];
    const float* fbe = (const float*)d_in[4];
    const float* fm  = (const float*)d_in[5];
    const float* fv  = (const float*)d_in[6];
    const float* wG  = (const float*)d_in[7];
    const float* bG  = (const float*)d_in[8];
    const float* gw  = (const float*)d_in[9];
    const float* gbe = (const float*)d_in[10];
    const float* gm  = (const float*)d_in[11];
    const float* gv  = (const float*)d_in[12];
    const float* wH  = (const float*)d_in[13];
    const float* bH  = (const float*)d_in[14];
    const float* hw  = (const float*)d_in[15];
    const float* hbe = (const float*)d_in[16];
    const float* hm  = (const float*)d_in[17];
    const float* hv  = (const float*)d_in[18];
    const float* gamma = (const float*)d_in[19];
    float* out = (float*)d_out;

    cudaFuncSetAttribute(gemm_se_kernel,
                         cudaFuncAttributeMaxDynamicSharedMemorySize, SE_SMEM);
    cudaFuncSetAttribute(gemm_o_mma_kernel,
                         cudaFuncAttributeMaxDynamicSharedMemorySize, SMEM_DYN);

    proj_kernel<<<dim3(NN / 64, BB), 256>>>(x,
        wF, bF, fw, fbe, fm, fv,
        wG, bG, gw, gbe, gm, gv,
        wH, bH, hw, hbe, hm, hv);
    norms_kernel<<<dim3(NN / 256, BB), 256>>>();
    gemm_se_kernel<<<dim3(NN / 128, NN / 128, BB), 256, SE_SMEM>>>();
    reduce_sum_kernel<<<BB * NN / 8, 256>>>();
    scale_h_kernel<<<BB * CPAD, 256>>>();
    gemm_o_mma_kernel<<<dim3(NN / 128, BB), 256, SMEM_DYN>>>(x, gamma, out);
}